// round 3
// baseline (speedup 1.0000x reference)
#include <cuda_runtime.h>
#include <cuda_bf16.h>
#include <math.h>

// Problem constants
#define BATCH 4
#define SEQ   2048
#define EMB   1024
#define HEADS 16
#define HDIM  64
#define MROWS (BATCH * SEQ)          // 8192
#define ATT_SCALE 0.125f             // 1/sqrt(64)

// Scratch buffers (device globals: allocation-free per harness rules)
__device__ float g_q[MROWS * EMB];
__device__ float g_k[MROWS * EMB];
__device__ float g_v[MROWS * EMB];
__device__ float g_att[MROWS * EMB];

// ---------------------------------------------------------------------------
// SGEMM with bias: C[M,N] = A[M,K] @ W[K,N] + bias[N]
// BM=128, BN=128, BK=8, 256 threads, 8x8 per thread. All dims divisible.
// ---------------------------------------------------------------------------
__global__ __launch_bounds__(256) void sgemm_bias(
    const float* __restrict__ A, const float* __restrict__ W,
    const float* __restrict__ bias, float* __restrict__ C,
    int M, int N, int K)
{
    const int tid = threadIdx.x;
    const int bm = blockIdx.y;
    const int bn = blockIdx.x;

    __shared__ float As[8][128];   // transposed A tile
    __shared__ float Ws[8][128];

    const int arow = tid >> 1;          // 0..127
    const int acol = (tid & 1) << 2;    // 0 or 4
    const int wrow = tid >> 5;          // 0..7
    const int wcol = (tid & 31) << 2;   // 0,4,...,124

    const int ty = (tid >> 4) << 3;     // 0..120 step 8
    const int tx = (tid & 15) << 3;

    float acc[8][8];
    #pragma unroll
    for (int i = 0; i < 8; i++)
        #pragma unroll
        for (int j = 0; j < 8; j++) acc[i][j] = 0.f;

    const float* Ag = A + (size_t)(bm * 128 + arow) * K + acol;
    const float* Wg = W + (size_t)wrow * N + bn * 128 + wcol;

    for (int k0 = 0; k0 < K; k0 += 8) {
        float4 a = *(const float4*)(Ag + k0);
        As[acol + 0][arow] = a.x;
        As[acol + 1][arow] = a.y;
        As[acol + 2][arow] = a.z;
        As[acol + 3][arow] = a.w;
        float4 w = *(const float4*)(Wg + (size_t)k0 * N);
        *(float4*)&Ws[wrow][wcol] = w;
        __syncthreads();

        #pragma unroll
        for (int kk = 0; kk < 8; kk++) {
            float rm[8], rn[8];
            #pragma unroll
            for (int i = 0; i < 8; i++) rm[i] = As[kk][ty + i];
            #pragma unroll
            for (int j = 0; j < 8; j++) rn[j] = Ws[kk][tx + j];
            #pragma unroll
            for (int i = 0; i < 8; i++)
                #pragma unroll
                for (int j = 0; j < 8; j++)
                    acc[i][j] = fmaf(rm[i], rn[j], acc[i][j]);
        }
        __syncthreads();
    }

    // Epilogue: add bias, store as float4 pairs
    #pragma unroll
    for (int i = 0; i < 8; i++) {
        float* Crow = C + (size_t)(bm * 128 + ty + i) * N + bn * 128 + tx;
        const float* brow = bias + bn * 128 + tx;
        #pragma unroll
        for (int j = 0; j < 8; j += 4) {
            float4 o;
            o.x = acc[i][j + 0] + brow[j + 0];
            o.y = acc[i][j + 1] + brow[j + 1];
            o.z = acc[i][j + 2] + brow[j + 2];
            o.w = acc[i][j + 3] + brow[j + 3];
            *(float4*)(Crow + j) = o;
        }
    }
}

// ---------------------------------------------------------------------------
// Causal flash attention, fp32.
// Grid: (SEQ/128, BATCH*HEADS). 128 threads; thread t owns query row m0+t.
// Q row and output accumulator in registers; K/V tiles (64 rows) in smem.
// Per-element online softmax: rescale branch fires only on a new row max.
// ---------------------------------------------------------------------------
__global__ __launch_bounds__(128) void flash_causal(
    const float* __restrict__ Qp, const float* __restrict__ Kp,
    const float* __restrict__ Vp, float* __restrict__ Op)
{
    const int bh = blockIdx.y;
    const int b  = bh >> 4;        // /16
    const int h  = bh & 15;
    const int m0 = blockIdx.x * 128;
    const int t  = threadIdx.x;
    const int row = m0 + t;

    __shared__ float4 Ks[64 * 16];   // 64 rows x 64 floats
    __shared__ float4 Vs[64 * 16];

    // Load this thread's Q row into registers
    const float4* Qg = (const float4*)(Qp + ((size_t)(b * SEQ + row) * EMB + h * HDIM));
    float4 q4[16];
    #pragma unroll
    for (int i = 0; i < 16; i++) q4[i] = Qg[i];

    float4 out4[16];
    #pragma unroll
    for (int i = 0; i < 16; i++) out4[i] = make_float4(0.f, 0.f, 0.f, 0.f);
    float mrow = -INFINITY;
    float lrow = 0.f;

    const float4* Kg = (const float4*)(Kp + ((size_t)(b * SEQ) * EMB + h * HDIM));
    const float4* Vg = (const float4*)(Vp + ((size_t)(b * SEQ) * EMB + h * HDIM));
    const int rowstride4 = EMB / 4;  // 256 float4 per seq row

    const int nEnd = m0 + 128;       // causal: keys <= max row in this block
    for (int n0 = 0; n0 < nEnd; n0 += 64) {
        // Cooperative tile load: 64 rows x 16 float4 = 1024 float4, 8 per thread
        #pragma unroll
        for (int i = 0; i < 8; i++) {
            int idx = t + i * 128;
            int r = idx >> 4;
            int c = idx & 15;
            Ks[idx] = Kg[(size_t)(n0 + r) * rowstride4 + c];
            Vs[idx] = Vg[(size_t)(n0 + r) * rowstride4 + c];
        }
        __syncthreads();

        const bool full = (n0 + 64 <= m0 + 1);  // tile fully below diagonal for all rows

        for (int n = 0; n < 64; n++) {
            if (!full && (n0 + n > row)) break;
            // score = q . K[n]
            float dot = 0.f;
            #pragma unroll
            for (int kk = 0; kk < 16; kk++) {
                float4 kv = Ks[n * 16 + kk];
                dot = fmaf(q4[kk].x, kv.x, dot);
                dot = fmaf(q4[kk].y, kv.y, dot);
                dot = fmaf(q4[kk].z, kv.z, dot);
                dot = fmaf(q4[kk].w, kv.w, dot);
            }
            float s = dot * ATT_SCALE;
            if (s > mrow) {
                float corr = __expf(mrow - s);  // expf(-inf)=0 handles first iter
                mrow = s;
                lrow *= corr;
                #pragma unroll
                for (int dd = 0; dd < 16; dd++) {
                    out4[dd].x *= corr; out4[dd].y *= corr;
                    out4[dd].z *= corr; out4[dd].w *= corr;
                }
            }
            float p = __expf(s - mrow);
            lrow += p;
            #pragma unroll
            for (int dd = 0; dd < 16; dd++) {
                float4 vv = Vs[n * 16 + dd];
                out4[dd].x = fmaf(p, vv.x, out4[dd].x);
                out4[dd].y = fmaf(p, vv.y, out4[dd].y);
                out4[dd].z = fmaf(p, vv.z, out4[dd].z);
                out4[dd].w = fmaf(p, vv.w, out4[dd].w);
            }
        }
        __syncthreads();
    }

    const float inv = 1.f / lrow;
    float4* Og = (float4*)(Op + ((size_t)(b * SEQ + row) * EMB + h * HDIM));
    #pragma unroll
    for (int dd = 0; dd < 16; dd++) {
        float4 o = out4[dd];
        o.x *= inv; o.y *= inv; o.z *= inv; o.w *= inv;
        Og[dd] = o;
    }
}

// ---------------------------------------------------------------------------
// Launch
// ---------------------------------------------------------------------------
extern "C" void kernel_launch(void* const* d_in, const int* in_sizes, int n_in,
                              void* d_out, int out_size)
{
    const float* Q  = (const float*)d_in[0];
    const float* K  = (const float*)d_in[1];
    const float* V  = (const float*)d_in[2];
    const float* WQ = (const float*)d_in[3];
    const float* bQ = (const float*)d_in[4];
    const float* WK = (const float*)d_in[5];
    const float* bK = (const float*)d_in[6];
    const float* WV = (const float*)d_in[7];
    const float* bV = (const float*)d_in[8];
    const float* WO = (const float*)d_in[9];
    const float* bO = (const float*)d_in[10];
    float* out = (float*)d_out;

    float *gq, *gk, *gv, *ga;
    cudaGetSymbolAddress((void**)&gq, g_q);
    cudaGetSymbolAddress((void**)&gk, g_k);
    cudaGetSymbolAddress((void**)&gv, g_v);
    cudaGetSymbolAddress((void**)&ga, g_att);

    dim3 gg(EMB / 128, MROWS / 128);   // (8, 64)
    dim3 gb(256);

    sgemm_bias<<<gg, gb>>>(Q, WQ, bQ, gq, MROWS, EMB, EMB);
    sgemm_bias<<<gg, gb>>>(K, WK, bK, gk, MROWS, EMB, EMB);
    sgemm_bias<<<gg, gb>>>(V, WV, bV, gv, MROWS, EMB, EMB);

    dim3 fg(SEQ / 128, BATCH * HEADS); // (16, 64)
    flash_causal<<<fg, 128>>>(gq, gk, gv, ga);

    sgemm_bias<<<gg, gb>>>(ga, WO, bO, out, MROWS, EMB, EMB);
}

// round 4
// speedup vs baseline: 1.1415x; 1.1415x over previous
#include <cuda_runtime.h>
#include <cuda_bf16.h>
#include <math.h>
#include <stdint.h>

// Problem constants
#define BATCH 4
#define SEQ   2048
#define EMB   1024
#define HEADS 16
#define HDIM  64
#define MROWS (BATCH * SEQ)          // 8192
#define ATT_SCALE 0.125f             // 1/sqrt(64)

// Scratch buffers (device globals: allocation-free per harness rules)
__device__ float g_q[MROWS * EMB];
__device__ float g_k[MROWS * EMB];
__device__ float g_v[MROWS * EMB];
__device__ float g_att[MROWS * EMB];

// ---------------------------------------------------------------------------
// TF32 helpers
// ---------------------------------------------------------------------------
__device__ __forceinline__ float to_tf32(float x) {
    uint32_t u;
    asm("cvt.rna.tf32.f32 %0, %1;" : "=r"(u) : "f"(x));
    return __uint_as_float(u);
}

__device__ __forceinline__ void mma_tf32(float* c, const uint32_t* a, const uint32_t* b) {
    asm volatile(
        "mma.sync.aligned.m16n8k8.row.col.f32.tf32.tf32.f32 "
        "{%0,%1,%2,%3}, {%4,%5,%6,%7}, {%8,%9}, {%0,%1,%2,%3};\n"
        : "+f"(c[0]), "+f"(c[1]), "+f"(c[2]), "+f"(c[3])
        : "r"(a[0]), "r"(a[1]), "r"(a[2]), "r"(a[3]),
          "r"(b[0]), "r"(b[1]));
}

// ---------------------------------------------------------------------------
// TF32 tensor-core GEMM with bias: C[M,N] = A[M,K] @ W[K,N] + bias[N]
// BM=128, BN=128, BK=32, 256 threads (8 warps), warp tile 64x32,
// per warp 4 (m16) x 4 (n8) fragments, m16n8k8 tf32 mma.
// Register-prefetch single-buffer pipeline; cvt.rna at smem store.
// ---------------------------------------------------------------------------
__global__ __launch_bounds__(256, 2) void gemm_tf32_bias(
    const float* __restrict__ A, const float* __restrict__ W,
    const float* __restrict__ bias, float* __restrict__ C,
    int M, int N, int K)
{
    __shared__ float As[128][36];   // [m][k], pad -> bank=(4r+c)%32 conflict-free
    __shared__ float Bs[32][136];   // [k][n], pad -> bank=(8k+n)%32 conflict-free

    const int tid  = threadIdx.x;
    const int lane = tid & 31;
    const int wid  = tid >> 5;      // 0..7
    const int wm   = wid & 1;       // 2 warps along M (64 each)
    const int wn   = wid >> 1;      // 4 warps along N (32 each)
    const int bm   = blockIdx.y;
    const int bn   = blockIdx.x;

    const int grp = lane >> 2;      // 0..7
    const int tig = lane & 3;       // 0..3

    float acc[4][4][4];
    #pragma unroll
    for (int i = 0; i < 4; i++)
        #pragma unroll
        for (int j = 0; j < 4; j++)
            #pragma unroll
            for (int q = 0; q < 4; q++) acc[i][j][q] = 0.f;

    // gmem load indexing (4 float4 each for A and B per thread)
    // A: idx = tid + 256*i -> r = idx>>3 (0..127), c4 = idx&7 (col = 4*c4)
    // B: idx = tid + 256*i -> r = idx>>5 (0..31),  c4 = idx&31 (col = 4*c4)
    float4 pa[4], pb[4];

    const float* Abase = A + (size_t)(bm * 128) * K;
    const float* Wbase = W + bn * 128;

    // prologue: load k0 = 0
    #pragma unroll
    for (int i = 0; i < 4; i++) {
        int idx = tid + 256 * i;
        pa[i] = *(const float4*)(Abase + (size_t)(idx >> 3) * K + ((idx & 7) << 2));
        pb[i] = *(const float4*)(Wbase + (size_t)(idx >> 5) * N + ((idx & 31) << 2));
    }
    #pragma unroll
    for (int i = 0; i < 4; i++) {
        int idx = tid + 256 * i;
        int ra = idx >> 3, ca = (idx & 7) << 2;
        As[ra][ca + 0] = to_tf32(pa[i].x);
        As[ra][ca + 1] = to_tf32(pa[i].y);
        As[ra][ca + 2] = to_tf32(pa[i].z);
        As[ra][ca + 3] = to_tf32(pa[i].w);
        int rb = idx >> 5, cb = (idx & 31) << 2;
        Bs[rb][cb + 0] = to_tf32(pb[i].x);
        Bs[rb][cb + 1] = to_tf32(pb[i].y);
        Bs[rb][cb + 2] = to_tf32(pb[i].z);
        Bs[rb][cb + 3] = to_tf32(pb[i].w);
    }
    __syncthreads();

    for (int k0 = 0; k0 < K; k0 += 32) {
        const bool more = (k0 + 32 < K);
        if (more) {
            #pragma unroll
            for (int i = 0; i < 4; i++) {
                int idx = tid + 256 * i;
                pa[i] = *(const float4*)(Abase + (size_t)(idx >> 3) * K + k0 + 32 + ((idx & 7) << 2));
                pb[i] = *(const float4*)(Wbase + (size_t)(k0 + 32 + (idx >> 5)) * N + ((idx & 31) << 2));
            }
        }

        // compute 4 k-steps of 8
        #pragma unroll
        for (int ks = 0; ks < 4; ks++) {
            const int kb = ks * 8;
            uint32_t af[4][4];
            #pragma unroll
            for (int mf = 0; mf < 4; mf++) {
                int r = wm * 64 + mf * 16 + grp;
                int c = kb + tig;
                af[mf][0] = __float_as_uint(As[r    ][c    ]);
                af[mf][1] = __float_as_uint(As[r + 8][c    ]);
                af[mf][2] = __float_as_uint(As[r    ][c + 4]);
                af[mf][3] = __float_as_uint(As[r + 8][c + 4]);
            }
            uint32_t bf[4][2];
            #pragma unroll
            for (int nf = 0; nf < 4; nf++) {
                int kr = kb + tig;
                int cn = wn * 32 + nf * 8 + grp;
                bf[nf][0] = __float_as_uint(Bs[kr    ][cn]);
                bf[nf][1] = __float_as_uint(Bs[kr + 4][cn]);
            }
            #pragma unroll
            for (int mf = 0; mf < 4; mf++)
                #pragma unroll
                for (int nf = 0; nf < 4; nf++)
                    mma_tf32(acc[mf][nf], af[mf], bf[nf]);
        }

        if (more) {
            __syncthreads();
            #pragma unroll
            for (int i = 0; i < 4; i++) {
                int idx = tid + 256 * i;
                int ra = idx >> 3, ca = (idx & 7) << 2;
                As[ra][ca + 0] = to_tf32(pa[i].x);
                As[ra][ca + 1] = to_tf32(pa[i].y);
                As[ra][ca + 2] = to_tf32(pa[i].z);
                As[ra][ca + 3] = to_tf32(pa[i].w);
                int rb = idx >> 5, cb = (idx & 31) << 2;
                Bs[rb][cb + 0] = to_tf32(pb[i].x);
                Bs[rb][cb + 1] = to_tf32(pb[i].y);
                Bs[rb][cb + 2] = to_tf32(pb[i].z);
                Bs[rb][cb + 3] = to_tf32(pb[i].w);
            }
            __syncthreads();
        }
    }

    // epilogue: bias + store (float2 per fragment half)
    float2 bb[4];
    #pragma unroll
    for (int nf = 0; nf < 4; nf++) {
        int col = bn * 128 + wn * 32 + nf * 8 + tig * 2;
        bb[nf] = *(const float2*)(bias + col);
    }
    #pragma unroll
    for (int mf = 0; mf < 4; mf++) {
        int row0 = bm * 128 + wm * 64 + mf * 16 + grp;
        #pragma unroll
        for (int nf = 0; nf < 4; nf++) {
            int col = bn * 128 + wn * 32 + nf * 8 + tig * 2;
            float2 v0, v1;
            v0.x = acc[mf][nf][0] + bb[nf].x;
            v0.y = acc[mf][nf][1] + bb[nf].y;
            v1.x = acc[mf][nf][2] + bb[nf].x;
            v1.y = acc[mf][nf][3] + bb[nf].y;
            *(float2*)(C + (size_t)row0 * N + col)       = v0;
            *(float2*)(C + (size_t)(row0 + 8) * N + col) = v1;
        }
    }
}

// ---------------------------------------------------------------------------
// Causal flash attention, fp32, lane-pair split.
// Grid: (SEQ/128, BATCH*HEADS). 256 threads; lanes (2r, 2r+1) share query
// row m0+r, each owning 32 of the 64 head dims. Dot product is combined via
// shfl_xor(1); softmax state computed redundantly (identically) in both lanes.
// Warp-uniform inner trip count + per-lane validity predicate keeps
// shfl_xor_sync(0xffffffff) legal under causal masking.
// ---------------------------------------------------------------------------
__global__ __launch_bounds__(256, 2) void flash_causal(
    const float* __restrict__ Qp, const float* __restrict__ Kp,
    const float* __restrict__ Vp, float* __restrict__ Op)
{
    const int bh = blockIdx.y;
    const int b  = bh >> 4;
    const int h  = bh & 15;
    const int m0 = blockIdx.x * 128;
    const int t  = threadIdx.x;      // 0..255
    const int r    = t >> 1;         // 0..127 query row within block
    const int half = t & 1;          // which 32-dim half
    const int row  = m0 + r;
    const int w    = t >> 5;         // warp id 0..7; warp covers rows [16w,16w+15]

    __shared__ float4 Ks[64 * 16];   // 64 rows x 64 floats
    __shared__ float4 Vs[64 * 16];

    const float4* Qg = (const float4*)(Qp + ((size_t)(b * SEQ + row) * EMB + h * HDIM));
    float4 q4[8];
    #pragma unroll
    for (int i = 0; i < 8; i++) q4[i] = Qg[half * 8 + i];

    float4 out4[8];
    #pragma unroll
    for (int i = 0; i < 8; i++) out4[i] = make_float4(0.f, 0.f, 0.f, 0.f);
    float mrow = -INFINITY;
    float lrow = 0.f;

    const float4* Kg = (const float4*)(Kp + ((size_t)(b * SEQ) * EMB + h * HDIM));
    const float4* Vg = (const float4*)(Vp + ((size_t)(b * SEQ) * EMB + h * HDIM));
    const int rowstride4 = EMB / 4;  // 256 float4 per seq row

    const int rowMaxWarp = m0 + w * 16 + 15;

    const int nEnd = m0 + 128;
    for (int n0 = 0; n0 < nEnd; n0 += 64) {
        // Cooperative tile load: 2048 float4 over 256 threads = 8 each
        #pragma unroll
        for (int i = 0; i < 4; i++) {
            int idx = t + i * 256;
            int rr = idx >> 4;
            int cc = idx & 15;
            Ks[idx] = Kg[(size_t)(n0 + rr) * rowstride4 + cc];
            Vs[idx] = Vg[(size_t)(n0 + rr) * rowstride4 + cc];
        }
        __syncthreads();

        const bool full = (n0 + 64 <= m0 + 1);  // whole tile below diagonal for all rows
        int nCap = 64;
        if (!full) {
            nCap = rowMaxWarp - n0 + 1;
            if (nCap > 64) nCap = 64;
            if (nCap < 0) nCap = 0;
        }

        for (int n = 0; n < nCap; n++) {
            // partial dot over this lane's 32 dims
            float dot = 0.f;
            #pragma unroll
            for (int kk = 0; kk < 8; kk++) {
                float4 kv = Ks[n * 16 + half * 8 + kk];
                dot = fmaf(q4[kk].x, kv.x, dot);
                dot = fmaf(q4[kk].y, kv.y, dot);
                dot = fmaf(q4[kk].z, kv.z, dot);
                dot = fmaf(q4[kk].w, kv.w, dot);
            }
            dot += __shfl_xor_sync(0xffffffffu, dot, 1);
            float s = dot * ATT_SCALE;

            bool valid = full || (n0 + n <= row);
            if (valid) {
                if (s > mrow) {
                    float corr = __expf(mrow - s);  // expf(-inf)=0 on first hit
                    mrow = s;
                    lrow *= corr;
                    #pragma unroll
                    for (int dd = 0; dd < 8; dd++) {
                        out4[dd].x *= corr; out4[dd].y *= corr;
                        out4[dd].z *= corr; out4[dd].w *= corr;
                    }
                }
                float p = __expf(s - mrow);
                lrow += p;
                #pragma unroll
                for (int dd = 0; dd < 8; dd++) {
                    float4 vv = Vs[n * 16 + half * 8 + dd];
                    out4[dd].x = fmaf(p, vv.x, out4[dd].x);
                    out4[dd].y = fmaf(p, vv.y, out4[dd].y);
                    out4[dd].z = fmaf(p, vv.z, out4[dd].z);
                    out4[dd].w = fmaf(p, vv.w, out4[dd].w);
                }
            }
        }
        __syncthreads();
    }

    const float inv = 1.f / lrow;
    float4* Og = (float4*)(Op + ((size_t)(b * SEQ + row) * EMB + h * HDIM));
    #pragma unroll
    for (int dd = 0; dd < 8; dd++) {
        float4 o = out4[dd];
        o.x *= inv; o.y *= inv; o.z *= inv; o.w *= inv;
        Og[half * 8 + dd] = o;
    }
}

// ---------------------------------------------------------------------------
// Launch
// ---------------------------------------------------------------------------
extern "C" void kernel_launch(void* const* d_in, const int* in_sizes, int n_in,
                              void* d_out, int out_size)
{
    const float* Q  = (const float*)d_in[0];
    const float* K  = (const float*)d_in[1];
    const float* V  = (const float*)d_in[2];
    const float* WQ = (const float*)d_in[3];
    const float* bQ = (const float*)d_in[4];
    const float* WK = (const float*)d_in[5];
    const float* bK = (const float*)d_in[6];
    const float* WV = (const float*)d_in[7];
    const float* bV = (const float*)d_in[8];
    const float* WO = (const float*)d_in[9];
    const float* bO = (const float*)d_in[10];
    float* out = (float*)d_out;

    float *gq, *gk, *gv, *ga;
    cudaGetSymbolAddress((void**)&gq, g_q);
    cudaGetSymbolAddress((void**)&gk, g_k);
    cudaGetSymbolAddress((void**)&gv, g_v);
    cudaGetSymbolAddress((void**)&ga, g_att);

    dim3 gg(EMB / 128, MROWS / 128);   // (8, 64)
    dim3 gb(256);

    gemm_tf32_bias<<<gg, gb>>>(Q, WQ, bQ, gq, MROWS, EMB, EMB);
    gemm_tf32_bias<<<gg, gb>>>(K, WK, bK, gk, MROWS, EMB, EMB);
    gemm_tf32_bias<<<gg, gb>>>(V, WV, bV, gv, MROWS, EMB, EMB);

    dim3 fg(SEQ / 128, BATCH * HEADS); // (16, 64)
    flash_causal<<<fg, 256>>>(gq, gk, gv, ga);

    gemm_tf32_bias<<<gg, gb>>>(ga, WO, bO, out, MROWS, EMB, EMB);
}

// round 7
// speedup vs baseline: 3.4421x; 3.0154x over previous
#include <cuda_runtime.h>
#include <cuda_bf16.h>
#include <math.h>
#include <stdint.h>

// Problem constants
#define BATCH 4
#define SEQ   2048
#define EMB   1024
#define HEADS 16
#define HDIM  64
#define MROWS (BATCH * SEQ)          // 8192
#define ATT_SCALE 0.125f             // 1/sqrt(64)
#define SLOG2 (0.125f * 1.4426950408889634f)   // scale * log2(e)

// Scratch buffers (device globals: allocation-free per harness rules)
__device__ float g_q[MROWS * EMB];
__device__ float g_k[MROWS * EMB];
__device__ float g_v[MROWS * EMB];
__device__ float g_att[MROWS * EMB];

// ---------------------------------------------------------------------------
// TF32 helpers
// ---------------------------------------------------------------------------
__device__ __forceinline__ float to_tf32(float x) {
    uint32_t u;
    asm("cvt.rna.tf32.f32 %0, %1;" : "=r"(u) : "f"(x));
    return __uint_as_float(u);
}
__device__ __forceinline__ float4 tf32x4(float4 v) {
    v.x = to_tf32(v.x); v.y = to_tf32(v.y);
    v.z = to_tf32(v.z); v.w = to_tf32(v.w);
    return v;
}
__device__ __forceinline__ float fast_exp2(float x) {
    float y;
    asm("ex2.approx.f32 %0, %1;" : "=f"(y) : "f"(x));
    return y;
}

__device__ __forceinline__ void mma_tf32(float* c, const uint32_t* a, const uint32_t* b) {
    asm volatile(
        "mma.sync.aligned.m16n8k8.row.col.f32.tf32.tf32.f32 "
        "{%0,%1,%2,%3}, {%4,%5,%6,%7}, {%8,%9}, {%0,%1,%2,%3};\n"
        : "+f"(c[0]), "+f"(c[1]), "+f"(c[2]), "+f"(c[3])
        : "r"(a[0]), "r"(a[1]), "r"(a[2]), "r"(a[3]),
          "r"(b[0]), "r"(b[1]));
}

// ---------------------------------------------------------------------------
// TF32 tensor-core GEMM with bias: C[M,N] = A[M,K] @ W[K,N] + bias[N]
// (validated)
// ---------------------------------------------------------------------------
__global__ __launch_bounds__(256, 2) void gemm_tf32_bias(
    const float* __restrict__ A, const float* __restrict__ W,
    const float* __restrict__ bias, float* __restrict__ C,
    int M, int N, int K)
{
    __shared__ float As[128][36];   // [m][k], bank=(4r+c)%32 conflict-free
    __shared__ float Bs[32][136];   // [k][n], bank=(8k+n)%32 conflict-free

    const int tid  = threadIdx.x;
    const int lane = tid & 31;
    const int wid  = tid >> 5;
    const int wm   = wid & 1;
    const int wn   = wid >> 1;
    const int bm   = blockIdx.y;
    const int bn   = blockIdx.x;

    const int grp = lane >> 2;
    const int tig = lane & 3;

    float acc[4][4][4];
    #pragma unroll
    for (int i = 0; i < 4; i++)
        #pragma unroll
        for (int j = 0; j < 4; j++)
            #pragma unroll
            for (int q = 0; q < 4; q++) acc[i][j][q] = 0.f;

    float4 pa[4], pb[4];
    const float* Abase = A + (size_t)(bm * 128) * K;
    const float* Wbase = W + bn * 128;

    #pragma unroll
    for (int i = 0; i < 4; i++) {
        int idx = tid + 256 * i;
        pa[i] = *(const float4*)(Abase + (size_t)(idx >> 3) * K + ((idx & 7) << 2));
        pb[i] = *(const float4*)(Wbase + (size_t)(idx >> 5) * N + ((idx & 31) << 2));
    }
    #pragma unroll
    for (int i = 0; i < 4; i++) {
        int idx = tid + 256 * i;
        int ra = idx >> 3, ca = (idx & 7) << 2;
        As[ra][ca + 0] = to_tf32(pa[i].x);
        As[ra][ca + 1] = to_tf32(pa[i].y);
        As[ra][ca + 2] = to_tf32(pa[i].z);
        As[ra][ca + 3] = to_tf32(pa[i].w);
        int rb = idx >> 5, cb = (idx & 31) << 2;
        Bs[rb][cb + 0] = to_tf32(pb[i].x);
        Bs[rb][cb + 1] = to_tf32(pb[i].y);
        Bs[rb][cb + 2] = to_tf32(pb[i].z);
        Bs[rb][cb + 3] = to_tf32(pb[i].w);
    }
    __syncthreads();

    for (int k0 = 0; k0 < K; k0 += 32) {
        const bool more = (k0 + 32 < K);
        if (more) {
            #pragma unroll
            for (int i = 0; i < 4; i++) {
                int idx = tid + 256 * i;
                pa[i] = *(const float4*)(Abase + (size_t)(idx >> 3) * K + k0 + 32 + ((idx & 7) << 2));
                pb[i] = *(const float4*)(Wbase + (size_t)(k0 + 32 + (idx >> 5)) * N + ((idx & 31) << 2));
            }
        }

        #pragma unroll
        for (int ks = 0; ks < 4; ks++) {
            const int kb = ks * 8;
            uint32_t af[4][4];
            #pragma unroll
            for (int mf = 0; mf < 4; mf++) {
                int r = wm * 64 + mf * 16 + grp;
                int c = kb + tig;
                af[mf][0] = __float_as_uint(As[r    ][c    ]);
                af[mf][1] = __float_as_uint(As[r + 8][c    ]);
                af[mf][2] = __float_as_uint(As[r    ][c + 4]);
                af[mf][3] = __float_as_uint(As[r + 8][c + 4]);
            }
            uint32_t bf[4][2];
            #pragma unroll
            for (int nf = 0; nf < 4; nf++) {
                int kr = kb + tig;
                int cn = wn * 32 + nf * 8 + grp;
                bf[nf][0] = __float_as_uint(Bs[kr    ][cn]);
                bf[nf][1] = __float_as_uint(Bs[kr + 4][cn]);
            }
            #pragma unroll
            for (int mf = 0; mf < 4; mf++)
                #pragma unroll
                for (int nf = 0; nf < 4; nf++)
                    mma_tf32(acc[mf][nf], af[mf], bf[nf]);
        }

        if (more) {
            __syncthreads();
            #pragma unroll
            for (int i = 0; i < 4; i++) {
                int idx = tid + 256 * i;
                int ra = idx >> 3, ca = (idx & 7) << 2;
                As[ra][ca + 0] = to_tf32(pa[i].x);
                As[ra][ca + 1] = to_tf32(pa[i].y);
                As[ra][ca + 2] = to_tf32(pa[i].z);
                As[ra][ca + 3] = to_tf32(pa[i].w);
                int rb = idx >> 5, cb = (idx & 31) << 2;
                Bs[rb][cb + 0] = to_tf32(pb[i].x);
                Bs[rb][cb + 1] = to_tf32(pb[i].y);
                Bs[rb][cb + 2] = to_tf32(pb[i].z);
                Bs[rb][cb + 3] = to_tf32(pb[i].w);
            }
            __syncthreads();
        }
    }

    float2 bb[4];
    #pragma unroll
    for (int nf = 0; nf < 4; nf++) {
        int col = bn * 128 + wn * 32 + nf * 8 + tig * 2;
        bb[nf] = *(const float2*)(bias + col);
    }
    #pragma unroll
    for (int mf = 0; mf < 4; mf++) {
        int row0 = bm * 128 + wm * 64 + mf * 16 + grp;
        #pragma unroll
        for (int nf = 0; nf < 4; nf++) {
            int col = bn * 128 + wn * 32 + nf * 8 + tig * 2;
            float2 v0, v1;
            v0.x = acc[mf][nf][0] + bb[nf].x;
            v0.y = acc[mf][nf][1] + bb[nf].y;
            v1.x = acc[mf][nf][2] + bb[nf].x;
            v1.y = acc[mf][nf][3] + bb[nf].y;
            *(float2*)(C + (size_t)row0 * N + col)       = v0;
            *(float2*)(C + (size_t)(row0 + 8) * N + col) = v1;
        }
    }
}

// ---------------------------------------------------------------------------
// Tensor-core causal flash attention (TF32 mma, FA2-style).
// Grid: (SEQ/128, BATCH*HEADS). 256 threads = 8 warps; warp w owns query
// rows [m0+16w, m0+16w+16). KV tiles of 64 keys. Q a-fragments persistent
// in registers; S and O in m16n8 c-fragments; P round-trips through smem.
// FIX vs R5: the softmax denominator partial sums s0/s1 are now reduced
// across the 4 lanes of each fragment row (shfl_xor 1,2). Previously each
// lane kept a 16-key partial sum; fully-masked lanes got ll=0 -> 1/0 -> NaN.
// ---------------------------------------------------------------------------
#define PS_STRIDE 68
#define KS_STRIDE 68
#define VS_STRIDE 72
#define OFF_KS (128 * PS_STRIDE)
#define OFF_VS (OFF_KS + 64 * KS_STRIDE)
#define SMEM_FLASH_BYTES ((OFF_VS + 64 * VS_STRIDE) * 4)   // 70656

__global__ __launch_bounds__(256, 1) void flash_tc(
    const float* __restrict__ Qp, const float* __restrict__ Kp,
    const float* __restrict__ Vp, float* __restrict__ Op)
{
    extern __shared__ float sm[];
    float* Ps = sm;
    float* Ks = sm + OFF_KS;
    float* Vs = sm + OFF_VS;

    const int bh = blockIdx.y;
    const int b  = bh >> 4, h = bh & 15;
    const int m0 = blockIdx.x * 128;
    const int t  = threadIdx.x, lane = t & 31, w = t >> 5;
    const int grp = lane >> 2, tig = lane & 3;

    const float* Qbase = Qp + (size_t)b * SEQ * EMB + h * HDIM;
    const float* Kbase = Kp + (size_t)b * SEQ * EMB + h * HDIM;
    const float* Vbase = Vp + (size_t)b * SEQ * EMB + h * HDIM;

    // Stage Q tile (rows m0..m0+127, this head's 64 dims) into Ps, tf32.
    #pragma unroll
    for (int i = 0; i < 8; i++) {
        int idx = t + i * 256;
        int r = idx >> 4, c4 = idx & 15;
        float4 v = *(const float4*)(Qbase + (size_t)(m0 + r) * EMB + c4 * 4);
        *(float4*)(Ps + r * PS_STRIDE + c4 * 4) = tf32x4(v);
    }
    __syncthreads();

    // Persistent Q a-fragments (m16k8 x 8 k-steps).
    const int qr = w * 16 + grp;
    uint32_t qf[8][4];
    #pragma unroll
    for (int kf = 0; kf < 8; kf++) {
        const float* p0 = Ps + qr * PS_STRIDE + kf * 8 + tig;
        const float* p1 = p0 + 8 * PS_STRIDE;
        qf[kf][0] = __float_as_uint(p0[0]);
        qf[kf][1] = __float_as_uint(p1[0]);
        qf[kf][2] = __float_as_uint(p0[4]);
        qf[kf][3] = __float_as_uint(p1[4]);
    }

    float of[8][4];
    #pragma unroll
    for (int nf = 0; nf < 8; nf++)
        #pragma unroll
        for (int q = 0; q < 4; q++) of[nf][q] = 0.f;
    float mm0 = -INFINITY, mm1 = -INFINITY, ll0 = 0.f, ll1 = 0.f;

    const int rowMin = m0 + w * 16;
    const int rowMax = rowMin + 15;
    const int i0 = rowMin + grp;   // global row of c0/c1
    const int i1 = i0 + 8;         // global row of c2/c3

    for (int n0 = 0; n0 < m0 + 128; n0 += 64) {
        __syncthreads();   // Ks/Vs reuse
        #pragma unroll
        for (int i = 0; i < 4; i++) {
            int idx = t + i * 256;
            int r = idx >> 4, c4 = idx & 15;
            float4 kv = *(const float4*)(Kbase + (size_t)(n0 + r) * EMB + c4 * 4);
            *(float4*)(Ks + r * KS_STRIDE + c4 * 4) = tf32x4(kv);
            float4 vv = *(const float4*)(Vbase + (size_t)(n0 + r) * EMB + c4 * 4);
            *(float4*)(Vs + r * VS_STRIDE + c4 * 4) = tf32x4(vv);
        }
        __syncthreads();

        if (n0 > rowMax) continue;   // warp-uniform skip (still hits syncs)

        // --- S = Q @ K^T  (c-frag: 16 rows x 64 keys per warp) ---
        float sf[8][4];
        #pragma unroll
        for (int nf = 0; nf < 8; nf++)
            #pragma unroll
            for (int q = 0; q < 4; q++) sf[nf][q] = 0.f;

        #pragma unroll
        for (int nf = 0; nf < 8; nf++) {
            const float* kb = Ks + (nf * 8 + grp) * KS_STRIDE + tig;
            #pragma unroll
            for (int kf = 0; kf < 8; kf++) {
                uint32_t bfr[2];
                bfr[0] = __float_as_uint(kb[kf * 8]);
                bfr[1] = __float_as_uint(kb[kf * 8 + 4]);
                mma_tf32(sf[nf], qf[kf], bfr);
            }
        }

        // --- scale (log2 space) + causal mask ---
        const bool fullT = (n0 + 63 <= rowMin);
        #pragma unroll
        for (int nf = 0; nf < 8; nf++) {
            #pragma unroll
            for (int q = 0; q < 4; q++) sf[nf][q] *= SLOG2;
            if (!fullT) {
                int j0 = n0 + nf * 8 + 2 * tig;
                if (j0     > i0) sf[nf][0] = -INFINITY;
                if (j0 + 1 > i0) sf[nf][1] = -INFINITY;
                if (j0     > i1) sf[nf][2] = -INFINITY;
                if (j0 + 1 > i1) sf[nf][3] = -INFINITY;
            }
        }

        // --- online softmax (rows live in 4 consecutive lanes) ---
        float mx0 = -INFINITY, mx1 = -INFINITY;
        #pragma unroll
        for (int nf = 0; nf < 8; nf++) {
            mx0 = fmaxf(mx0, fmaxf(sf[nf][0], sf[nf][1]));
            mx1 = fmaxf(mx1, fmaxf(sf[nf][2], sf[nf][3]));
        }
        mx0 = fmaxf(mx0, __shfl_xor_sync(0xffffffffu, mx0, 1));
        mx0 = fmaxf(mx0, __shfl_xor_sync(0xffffffffu, mx0, 2));
        mx1 = fmaxf(mx1, __shfl_xor_sync(0xffffffffu, mx1, 1));
        mx1 = fmaxf(mx1, __shfl_xor_sync(0xffffffffu, mx1, 2));

        float nm0 = fmaxf(mm0, mx0), nm1 = fmaxf(mm1, mx1);
        float c0 = fast_exp2(mm0 - nm0), c1 = fast_exp2(mm1 - nm1);
        mm0 = nm0; mm1 = nm1;

        float s0 = 0.f, s1 = 0.f;
        float* pr0 = Ps + qr * PS_STRIDE + 2 * tig;
        float* pr1 = pr0 + 8 * PS_STRIDE;
        #pragma unroll
        for (int nf = 0; nf < 8; nf++) {
            // round P to tf32; denominator accumulates the SAME rounded values
            float p00 = to_tf32(fast_exp2(sf[nf][0] - nm0));
            float p01 = to_tf32(fast_exp2(sf[nf][1] - nm0));
            float p10 = to_tf32(fast_exp2(sf[nf][2] - nm1));
            float p11 = to_tf32(fast_exp2(sf[nf][3] - nm1));
            s0 += p00 + p01;
            s1 += p10 + p11;
            *(float2*)(pr0 + nf * 8) = make_float2(p00, p01);
            *(float2*)(pr1 + nf * 8) = make_float2(p10, p11);
            of[nf][0] *= c0; of[nf][1] *= c0;
            of[nf][2] *= c1; of[nf][3] *= c1;
        }
        // FIX: reduce partial denominators across the 4 lanes of each row
        s0 += __shfl_xor_sync(0xffffffffu, s0, 1);
        s0 += __shfl_xor_sync(0xffffffffu, s0, 2);
        s1 += __shfl_xor_sync(0xffffffffu, s1, 1);
        s1 += __shfl_xor_sync(0xffffffffu, s1, 2);
        ll0 = ll0 * c0 + s0;
        ll1 = ll1 * c1 + s1;
        __syncwarp();   // P rows are warp-private: syncwarp suffices

        // --- O += P @ V ---
        uint32_t af[8][4];
        #pragma unroll
        for (int kf = 0; kf < 8; kf++) {
            const float* a0 = Ps + qr * PS_STRIDE + kf * 8 + tig;
            const float* a1 = a0 + 8 * PS_STRIDE;
            af[kf][0] = __float_as_uint(a0[0]);
            af[kf][1] = __float_as_uint(a1[0]);
            af[kf][2] = __float_as_uint(a0[4]);
            af[kf][3] = __float_as_uint(a1[4]);
        }
        #pragma unroll
        for (int nf = 0; nf < 8; nf++) {
            #pragma unroll
            for (int kf = 0; kf < 8; kf++) {
                uint32_t bfr[2];
                const float* vb = Vs + (kf * 8 + tig) * VS_STRIDE + nf * 8 + grp;
                bfr[0] = __float_as_uint(vb[0]);
                bfr[1] = __float_as_uint(vb[4 * VS_STRIDE]);
                mma_tf32(of[nf], af[kf], bfr);
            }
        }
    }

    // --- epilogue: normalize and store ---
    const float inv0 = 1.f / ll0;
    const float inv1 = 1.f / ll1;
    float* O0 = Op + (size_t)(b * SEQ + m0 + w * 16 + grp) * EMB + h * HDIM + 2 * tig;
    float* O1 = O0 + (size_t)8 * EMB;
    #pragma unroll
    for (int nf = 0; nf < 8; nf++) {
        *(float2*)(O0 + nf * 8) = make_float2(of[nf][0] * inv0, of[nf][1] * inv0);
        *(float2*)(O1 + nf * 8) = make_float2(of[nf][2] * inv1, of[nf][3] * inv1);
    }
}

// ---------------------------------------------------------------------------
// Launch
// ---------------------------------------------------------------------------
extern "C" void kernel_launch(void* const* d_in, const int* in_sizes, int n_in,
                              void* d_out, int out_size)
{
    const float* Q  = (const float*)d_in[0];
    const float* K  = (const float*)d_in[1];
    const float* V  = (const float*)d_in[2];
    const float* WQ = (const float*)d_in[3];
    const float* bQ = (const float*)d_in[4];
    const float* WK = (const float*)d_in[5];
    const float* bK = (const float*)d_in[6];
    const float* WV = (const float*)d_in[7];
    const float* bV = (const float*)d_in[8];
    const float* WO = (const float*)d_in[9];
    const float* bO = (const float*)d_in[10];
    float* out = (float*)d_out;

    float *gq, *gk, *gv, *ga;
    cudaGetSymbolAddress((void**)&gq, g_q);
    cudaGetSymbolAddress((void**)&gk, g_k);
    cudaGetSymbolAddress((void**)&gv, g_v);
    cudaGetSymbolAddress((void**)&ga, g_att);

    cudaFuncSetAttribute(flash_tc, cudaFuncAttributeMaxDynamicSharedMemorySize,
                         SMEM_FLASH_BYTES);

    dim3 gg(EMB / 128, MROWS / 128);   // (8, 64)
    dim3 gb(256);

    gemm_tf32_bias<<<gg, gb>>>(Q, WQ, bQ, gq, MROWS, EMB, EMB);
    gemm_tf32_bias<<<gg, gb>>>(K, WK, bK, gk, MROWS, EMB, EMB);
    gemm_tf32_bias<<<gg, gb>>>(V, WV, bV, gv, MROWS, EMB, EMB);

    dim3 fg(SEQ / 128, BATCH * HEADS); // (16, 64)
    flash_tc<<<fg, 256, SMEM_FLASH_BYTES>>>(gq, gk, gv, ga);

    gemm_tf32_bias<<<gg, gb>>>(ga, WO, bO, out, MROWS, EMB, EMB);
}

// round 9
// speedup vs baseline: 4.1325x; 1.2006x over previous
#include <cuda_runtime.h>
#include <cuda_bf16.h>
#include <math.h>
#include <stdint.h>

// Problem constants
#define BATCH 4
#define SEQ   2048
#define EMB   1024
#define HEADS 16
#define HDIM  64
#define MROWS (BATCH * SEQ)          // 8192
#define ATT_SCALE 0.125f             // 1/sqrt(64)
#define SLOG2 (0.125f * 1.4426950408889634f)   // scale * log2(e)

// Scratch buffers (device globals: allocation-free per harness rules)
__device__ float g_q[MROWS * EMB];
__device__ float g_k[MROWS * EMB];
__device__ float g_v[MROWS * EMB];
__device__ float g_att[MROWS * EMB];

// ---------------------------------------------------------------------------
// TF32 helpers
// ---------------------------------------------------------------------------
__device__ __forceinline__ float to_tf32(float x) {
    uint32_t u;
    asm("cvt.rna.tf32.f32 %0, %1;" : "=r"(u) : "f"(x));
    return __uint_as_float(u);
}
__device__ __forceinline__ float4 tf32x4(float4 v) {
    v.x = to_tf32(v.x); v.y = to_tf32(v.y);
    v.z = to_tf32(v.z); v.w = to_tf32(v.w);
    return v;
}
__device__ __forceinline__ float fast_exp2(float x) {
    float y;
    asm("ex2.approx.f32 %0, %1;" : "=f"(y) : "f"(x));
    return y;
}

__device__ __forceinline__ void mma_tf32(float* c, const uint32_t* a, const uint32_t* b) {
    asm volatile(
        "mma.sync.aligned.m16n8k8.row.col.f32.tf32.tf32.f32 "
        "{%0,%1,%2,%3}, {%4,%5,%6,%7}, {%8,%9}, {%0,%1,%2,%3};\n"
        : "+f"(c[0]), "+f"(c[1]), "+f"(c[2]), "+f"(c[3])
        : "r"(a[0]), "r"(a[1]), "r"(a[2]), "r"(a[3]),
          "r"(b[0]), "r"(b[1]));
}

// ---------------------------------------------------------------------------
// TF32 tensor-core GEMM with bias, double-buffered smem, z-batched over up
// to 3 independent (A,W,bias,C) problems (QKV fusion kills wave-tail + gaps).
// BM=128, BN=128, BK=32, 256 threads, warp tile 64x32, m16n8k8.
// Dynamic smem: As[2][128][36] + Bs[2][32][136] = 71680 B. One sync/k-iter.
// ---------------------------------------------------------------------------
#define GEMM_SMEM_BYTES ((2 * 128 * 36 + 2 * 32 * 136) * 4)   // 71680
#define AS(s, r, c) smg[(s) * (128 * 36) + (r) * 36 + (c)]
#define BS(s, r, c) smg[(2 * 128 * 36) + (s) * (32 * 136) + (r) * 136 + (c)]

__global__ __launch_bounds__(256, 2) void gemm_tf32_bias3(
    const float* __restrict__ A0, const float* __restrict__ A1, const float* __restrict__ A2,
    const float* __restrict__ W0, const float* __restrict__ W1, const float* __restrict__ W2,
    const float* __restrict__ b0, const float* __restrict__ b1, const float* __restrict__ b2,
    float* __restrict__ C0, float* __restrict__ C1, float* __restrict__ C2,
    int M, int N, int K)
{
    extern __shared__ float smg[];

    const int z = blockIdx.z;
    const float* A    = (z == 0) ? A0 : (z == 1) ? A1 : A2;
    const float* W    = (z == 0) ? W0 : (z == 1) ? W1 : W2;
    const float* bias = (z == 0) ? b0 : (z == 1) ? b1 : b2;
    float*       C    = (z == 0) ? C0 : (z == 1) ? C1 : C2;

    const int tid  = threadIdx.x;
    const int lane = tid & 31;
    const int wid  = tid >> 5;
    const int wm   = wid & 1;
    const int wn   = wid >> 1;
    const int bm   = blockIdx.y;
    const int bn   = blockIdx.x;

    const int grp = lane >> 2;
    const int tig = lane & 3;

    float acc[4][4][4];
    #pragma unroll
    for (int i = 0; i < 4; i++)
        #pragma unroll
        for (int j = 0; j < 4; j++)
            #pragma unroll
            for (int q = 0; q < 4; q++) acc[i][j][q] = 0.f;

    float4 pa[4], pb[4];
    const float* Abase = A + (size_t)(bm * 128) * K;
    const float* Wbase = W + bn * 128;

    // prologue: k0 = 0 into stage 0
    #pragma unroll
    for (int i = 0; i < 4; i++) {
        int idx = tid + 256 * i;
        pa[i] = *(const float4*)(Abase + (size_t)(idx >> 3) * K + ((idx & 7) << 2));
        pb[i] = *(const float4*)(Wbase + (size_t)(idx >> 5) * N + ((idx & 31) << 2));
    }
    #pragma unroll
    for (int i = 0; i < 4; i++) {
        int idx = tid + 256 * i;
        int ra = idx >> 3, ca = (idx & 7) << 2;
        AS(0, ra, ca + 0) = to_tf32(pa[i].x);
        AS(0, ra, ca + 1) = to_tf32(pa[i].y);
        AS(0, ra, ca + 2) = to_tf32(pa[i].z);
        AS(0, ra, ca + 3) = to_tf32(pa[i].w);
        int rb = idx >> 5, cb = (idx & 31) << 2;
        BS(0, rb, cb + 0) = to_tf32(pb[i].x);
        BS(0, rb, cb + 1) = to_tf32(pb[i].y);
        BS(0, rb, cb + 2) = to_tf32(pb[i].z);
        BS(0, rb, cb + 3) = to_tf32(pb[i].w);
    }
    __syncthreads();

    int s = 0;
    for (int k0 = 0; k0 < K; k0 += 32) {
        const bool more = (k0 + 32 < K);
        if (more) {
            #pragma unroll
            for (int i = 0; i < 4; i++) {
                int idx = tid + 256 * i;
                pa[i] = *(const float4*)(Abase + (size_t)(idx >> 3) * K + k0 + 32 + ((idx & 7) << 2));
                pb[i] = *(const float4*)(Wbase + (size_t)(k0 + 32 + (idx >> 5)) * N + ((idx & 31) << 2));
            }
        }

        #pragma unroll
        for (int ks = 0; ks < 4; ks++) {
            const int kb = ks * 8;
            uint32_t af[4][4];
            #pragma unroll
            for (int mf = 0; mf < 4; mf++) {
                int r = wm * 64 + mf * 16 + grp;
                int c = kb + tig;
                af[mf][0] = __float_as_uint(AS(s, r,     c    ));
                af[mf][1] = __float_as_uint(AS(s, r + 8, c    ));
                af[mf][2] = __float_as_uint(AS(s, r,     c + 4));
                af[mf][3] = __float_as_uint(AS(s, r + 8, c + 4));
            }
            uint32_t bf[4][2];
            #pragma unroll
            for (int nf = 0; nf < 4; nf++) {
                int kr = kb + tig;
                int cn = wn * 32 + nf * 8 + grp;
                bf[nf][0] = __float_as_uint(BS(s, kr,     cn));
                bf[nf][1] = __float_as_uint(BS(s, kr + 4, cn));
            }
            #pragma unroll
            for (int mf = 0; mf < 4; mf++)
                #pragma unroll
                for (int nf = 0; nf < 4; nf++)
                    mma_tf32(acc[mf][nf], af[mf], bf[nf]);
        }

        if (more) {
            const int d = s ^ 1;
            #pragma unroll
            for (int i = 0; i < 4; i++) {
                int idx = tid + 256 * i;
                int ra = idx >> 3, ca = (idx & 7) << 2;
                AS(d, ra, ca + 0) = to_tf32(pa[i].x);
                AS(d, ra, ca + 1) = to_tf32(pa[i].y);
                AS(d, ra, ca + 2) = to_tf32(pa[i].z);
                AS(d, ra, ca + 3) = to_tf32(pa[i].w);
                int rb = idx >> 5, cb = (idx & 31) << 2;
                BS(d, rb, cb + 0) = to_tf32(pb[i].x);
                BS(d, rb, cb + 1) = to_tf32(pb[i].y);
                BS(d, rb, cb + 2) = to_tf32(pb[i].z);
                BS(d, rb, cb + 3) = to_tf32(pb[i].w);
            }
            __syncthreads();
            s = d;
        }
    }

    float2 bb[4];
    #pragma unroll
    for (int nf = 0; nf < 4; nf++) {
        int col = bn * 128 + wn * 32 + nf * 8 + tig * 2;
        bb[nf] = *(const float2*)(bias + col);
    }
    #pragma unroll
    for (int mf = 0; mf < 4; mf++) {
        int row0 = bm * 128 + wm * 64 + mf * 16 + grp;
        #pragma unroll
        for (int nf = 0; nf < 4; nf++) {
            int col = bn * 128 + wn * 32 + nf * 8 + tig * 2;
            float2 v0, v1;
            v0.x = acc[mf][nf][0] + bb[nf].x;
            v0.y = acc[mf][nf][1] + bb[nf].y;
            v1.x = acc[mf][nf][2] + bb[nf].x;
            v1.y = acc[mf][nf][3] + bb[nf].y;
            *(float2*)(C + (size_t)row0 * N + col)       = v0;
            *(float2*)(C + (size_t)(row0 + 8) * N + col) = v1;
        }
    }
}

// ---------------------------------------------------------------------------
// Tensor-core causal flash attention (TF32 mma, FA2-style).
// R8: BM 128 -> 64, 128 threads (4 warps x 16 query rows). Per-thread state
// unchanged (167 regs) -> 3 CTAs/SM (regs 64.1K/65.5K, smem 160K/228K),
// 12 resident warps instead of 8; CTA overlap hides load/sync phases.
// Smem (dynamic, 53248 B): Ps[64][68] (Q then P), Ks[64][68], Vs[64][72].
// ---------------------------------------------------------------------------
#define BM 64
#define PS_STRIDE 68
#define KS_STRIDE 68
#define VS_STRIDE 72
#define OFF_KS (BM * PS_STRIDE)
#define OFF_VS (OFF_KS + 64 * KS_STRIDE)
#define SMEM_FLASH_BYTES ((OFF_VS + 64 * VS_STRIDE) * 4)   // 53248

__global__ __launch_bounds__(128, 3) void flash_tc(
    const float* __restrict__ Qp, const float* __restrict__ Kp,
    const float* __restrict__ Vp, float* __restrict__ Op)
{
    extern __shared__ float sm[];
    float* Ps = sm;
    float* Ks = sm + OFF_KS;
    float* Vs = sm + OFF_VS;

    const int bh = blockIdx.y;
    const int b  = bh >> 4, h = bh & 15;
    const int m0 = blockIdx.x * BM;
    const int t  = threadIdx.x, lane = t & 31, w = t >> 5;   // w: 0..3
    const int grp = lane >> 2, tig = lane & 3;

    const float* Qbase = Qp + (size_t)b * SEQ * EMB + h * HDIM;
    const float* Kbase = Kp + (size_t)b * SEQ * EMB + h * HDIM;
    const float* Vbase = Vp + (size_t)b * SEQ * EMB + h * HDIM;

    // Stage Q tile (rows m0..m0+63) into Ps, tf32. 1024 float4 / 128 thr = 8.
    #pragma unroll
    for (int i = 0; i < 8; i++) {
        int idx = t + i * 128;
        int r = idx >> 4, c4 = idx & 15;
        float4 v = *(const float4*)(Qbase + (size_t)(m0 + r) * EMB + c4 * 4);
        *(float4*)(Ps + r * PS_STRIDE + c4 * 4) = tf32x4(v);
    }
    __syncthreads();

    // Persistent Q a-fragments (m16k8 x 8 k-steps).
    const int qr = w * 16 + grp;
    uint32_t qf[8][4];
    #pragma unroll
    for (int kf = 0; kf < 8; kf++) {
        const float* p0 = Ps + qr * PS_STRIDE + kf * 8 + tig;
        const float* p1 = p0 + 8 * PS_STRIDE;
        qf[kf][0] = __float_as_uint(p0[0]);
        qf[kf][1] = __float_as_uint(p1[0]);
        qf[kf][2] = __float_as_uint(p0[4]);
        qf[kf][3] = __float_as_uint(p1[4]);
    }

    float of[8][4];
    #pragma unroll
    for (int nf = 0; nf < 8; nf++)
        #pragma unroll
        for (int q = 0; q < 4; q++) of[nf][q] = 0.f;
    float mm0 = -INFINITY, mm1 = -INFINITY, ll0 = 0.f, ll1 = 0.f;

    const int rowMin = m0 + w * 16;
    const int rowMax = rowMin + 15;
    const int i0 = rowMin + grp;   // global row of c0/c1
    const int i1 = i0 + 8;         // global row of c2/c3

    for (int n0 = 0; n0 < m0 + BM; n0 += 64) {
        __syncthreads();   // Ks/Vs reuse
        // KV tile load: 2048 float4 / 128 thr = 8 pairs each
        #pragma unroll
        for (int i = 0; i < 8; i++) {
            int idx = t + i * 128;
            int r = idx >> 4, c4 = idx & 15;
            float4 kv = *(const float4*)(Kbase + (size_t)(n0 + r) * EMB + c4 * 4);
            *(float4*)(Ks + r * KS_STRIDE + c4 * 4) = tf32x4(kv);
            float4 vv = *(const float4*)(Vbase + (size_t)(n0 + r) * EMB + c4 * 4);
            *(float4*)(Vs + r * VS_STRIDE + c4 * 4) = tf32x4(vv);
        }
        __syncthreads();

        if (n0 > rowMax) continue;   // warp-uniform skip (still hits syncs)

        // --- S = Q @ K^T ---
        float sf[8][4];
        #pragma unroll
        for (int nf = 0; nf < 8; nf++)
            #pragma unroll
            for (int q = 0; q < 4; q++) sf[nf][q] = 0.f;

        #pragma unroll
        for (int nf = 0; nf < 8; nf++) {
            const float* kb = Ks + (nf * 8 + grp) * KS_STRIDE + tig;
            #pragma unroll
            for (int kf = 0; kf < 8; kf++) {
                uint32_t bfr[2];
                bfr[0] = __float_as_uint(kb[kf * 8]);
                bfr[1] = __float_as_uint(kb[kf * 8 + 4]);
                mma_tf32(sf[nf], qf[kf], bfr);
            }
        }

        // --- scale (log2 space) + causal mask ---
        const bool fullT = (n0 + 63 <= rowMin);
        #pragma unroll
        for (int nf = 0; nf < 8; nf++) {
            #pragma unroll
            for (int q = 0; q < 4; q++) sf[nf][q] *= SLOG2;
            if (!fullT) {
                int j0 = n0 + nf * 8 + 2 * tig;
                if (j0     > i0) sf[nf][0] = -INFINITY;
                if (j0 + 1 > i0) sf[nf][1] = -INFINITY;
                if (j0     > i1) sf[nf][2] = -INFINITY;
                if (j0 + 1 > i1) sf[nf][3] = -INFINITY;
            }
        }

        // --- online softmax (rows live in 4 consecutive lanes) ---
        float mx0 = -INFINITY, mx1 = -INFINITY;
        #pragma unroll
        for (int nf = 0; nf < 8; nf++) {
            mx0 = fmaxf(mx0, fmaxf(sf[nf][0], sf[nf][1]));
            mx1 = fmaxf(mx1, fmaxf(sf[nf][2], sf[nf][3]));
        }
        mx0 = fmaxf(mx0, __shfl_xor_sync(0xffffffffu, mx0, 1));
        mx0 = fmaxf(mx0, __shfl_xor_sync(0xffffffffu, mx0, 2));
        mx1 = fmaxf(mx1, __shfl_xor_sync(0xffffffffu, mx1, 1));
        mx1 = fmaxf(mx1, __shfl_xor_sync(0xffffffffu, mx1, 2));

        float nm0 = fmaxf(mm0, mx0), nm1 = fmaxf(mm1, mx1);
        float c0 = fast_exp2(mm0 - nm0), c1 = fast_exp2(mm1 - nm1);
        mm0 = nm0; mm1 = nm1;

        float s0 = 0.f, s1 = 0.f;
        float* pr0 = Ps + qr * PS_STRIDE + 2 * tig;
        float* pr1 = pr0 + 8 * PS_STRIDE;
        #pragma unroll
        for (int nf = 0; nf < 8; nf++) {
            // round P to tf32; denominator accumulates the SAME rounded values
            float p00 = to_tf32(fast_exp2(sf[nf][0] - nm0));
            float p01 = to_tf32(fast_exp2(sf[nf][1] - nm0));
            float p10 = to_tf32(fast_exp2(sf[nf][2] - nm1));
            float p11 = to_tf32(fast_exp2(sf[nf][3] - nm1));
            s0 += p00 + p01;
            s1 += p10 + p11;
            *(float2*)(pr0 + nf * 8) = make_float2(p00, p01);
            *(float2*)(pr1 + nf * 8) = make_float2(p10, p11);
            of[nf][0] *= c0; of[nf][1] *= c0;
            of[nf][2] *= c1; of[nf][3] *= c1;
        }
        // reduce partial denominators across the 4 lanes of each row
        s0 += __shfl_xor_sync(0xffffffffu, s0, 1);
        s0 += __shfl_xor_sync(0xffffffffu, s0, 2);
        s1 += __shfl_xor_sync(0xffffffffu, s1, 1);
        s1 += __shfl_xor_sync(0xffffffffu, s1, 2);
        ll0 = ll0 * c0 + s0;
        ll1 = ll1 * c1 + s1;
        __syncwarp();   // P rows are warp-private

        // --- O += P @ V ---
        uint32_t af[8][4];
        #pragma unroll
        for (int kf = 0; kf < 8; kf++) {
            const float* a0 = Ps + qr * PS_STRIDE + kf * 8 + tig;
            const float* a1 = a0 + 8 * PS_STRIDE;
            af[kf][0] = __float_as_uint(a0[0]);
            af[kf][1] = __float_as_uint(a1[0]);
            af[kf][2] = __float_as_uint(a0[4]);
            af[kf][3] = __float_as_uint(a1[4]);
        }
        #pragma unroll
        for (int nf = 0; nf < 8; nf++) {
            #pragma unroll
            for (int kf = 0; kf < 8; kf++) {
                uint32_t bfr[2];
                const float* vb = Vs + (kf * 8 + tig) * VS_STRIDE + nf * 8 + grp;
                bfr[0] = __float_as_uint(vb[0]);
                bfr[1] = __float_as_uint(vb[4 * VS_STRIDE]);
                mma_tf32(of[nf], af[kf], bfr);
            }
        }
    }

    // --- epilogue: normalize and store ---
    const float inv0 = 1.f / ll0;
    const float inv1 = 1.f / ll1;
    float* O0 = Op + (size_t)(b * SEQ + m0 + w * 16 + grp) * EMB + h * HDIM + 2 * tig;
    float* O1 = O0 + (size_t)8 * EMB;
    #pragma unroll
    for (int nf = 0; nf < 8; nf++) {
        *(float2*)(O0 + nf * 8) = make_float2(of[nf][0] * inv0, of[nf][1] * inv0);
        *(float2*)(O1 + nf * 8) = make_float2(of[nf][2] * inv1, of[nf][3] * inv1);
    }
}

// ---------------------------------------------------------------------------
// Launch
// ---------------------------------------------------------------------------
extern "C" void kernel_launch(void* const* d_in, const int* in_sizes, int n_in,
                              void* d_out, int out_size)
{
    const float* Q  = (const float*)d_in[0];
    const float* K  = (const float*)d_in[1];
    const float* V  = (const float*)d_in[2];
    const float* WQ = (const float*)d_in[3];
    const float* bQ = (const float*)d_in[4];
    const float* WK = (const float*)d_in[5];
    const float* bK = (const float*)d_in[6];
    const float* WV = (const float*)d_in[7];
    const float* bV = (const float*)d_in[8];
    const float* WO = (const float*)d_in[9];
    const float* bO = (const float*)d_in[10];
    float* out = (float*)d_out;

    float *gq, *gk, *gv, *ga;
    cudaGetSymbolAddress((void**)&gq, g_q);
    cudaGetSymbolAddress((void**)&gk, g_k);
    cudaGetSymbolAddress((void**)&gv, g_v);
    cudaGetSymbolAddress((void**)&ga, g_att);

    cudaFuncSetAttribute(gemm_tf32_bias3, cudaFuncAttributeMaxDynamicSharedMemorySize,
                         GEMM_SMEM_BYTES);
    cudaFuncSetAttribute(flash_tc, cudaFuncAttributeMaxDynamicSharedMemorySize,
                         SMEM_FLASH_BYTES);

    // Fused Q/K/V projections: grid.z selects the problem
    dim3 gqkv(EMB / 128, MROWS / 128, 3);  // (8, 64, 3)
    gemm_tf32_bias3<<<gqkv, 256, GEMM_SMEM_BYTES>>>(
        Q, K, V, WQ, WK, WV, bQ, bK, bV, gq, gk, gv, MROWS, EMB, EMB);

    dim3 fg(SEQ / BM, BATCH * HEADS);      // (32, 64)
    flash_tc<<<fg, 128, SMEM_FLASH_BYTES>>>(gq, gk, gv, ga);

    // Output projection (z-size 1)
    dim3 go(EMB / 128, MROWS / 128, 1);
    gemm_tf32_bias3<<<go, 256, GEMM_SMEM_BYTES>>>(
        ga, ga, ga, WO, WO, WO, bO, bO, bO, out, out, out, MROWS, EMB, EMB);
}

// round 10
// speedup vs baseline: 4.2675x; 1.0327x over previous
#include <cuda_runtime.h>
#include <cuda_bf16.h>
#include <math.h>
#include <stdint.h>

// Problem constants
#define BATCH 4
#define SEQ   2048
#define EMB   1024
#define HEADS 16
#define HDIM  64
#define MROWS (BATCH * SEQ)          // 8192
#define ATT_SCALE 0.125f             // 1/sqrt(64)
#define SLOG2 (0.125f * 1.4426950408889634f)   // scale * log2(e)

// Scratch buffers (device globals: allocation-free per harness rules)
__device__ float g_q[MROWS * EMB];
__device__ float g_k[MROWS * EMB];
__device__ float g_v[MROWS * EMB];
__device__ float g_att[MROWS * EMB];
// tf32-pre-rounded operands (bitwise-identical numerics vs cvt-at-STS)
__device__ float g_rq[MROWS * EMB];
__device__ float g_rk[MROWS * EMB];
__device__ float g_rv[MROWS * EMB];
__device__ float g_w[4 * EMB * EMB];

// ---------------------------------------------------------------------------
// TF32 helpers
// ---------------------------------------------------------------------------
__device__ __forceinline__ float to_tf32(float x) {
    uint32_t u;
    asm("cvt.rna.tf32.f32 %0, %1;" : "=r"(u) : "f"(x));
    return __uint_as_float(u);
}
__device__ __forceinline__ float4 tf32x4(float4 v) {
    v.x = to_tf32(v.x); v.y = to_tf32(v.y);
    v.z = to_tf32(v.z); v.w = to_tf32(v.w);
    return v;
}
__device__ __forceinline__ float fast_exp2(float x) {
    float y;
    asm("ex2.approx.f32 %0, %1;" : "=f"(y) : "f"(x));
    return y;
}
__device__ __forceinline__ void mma_tf32(float* c, const uint32_t* a, const uint32_t* b) {
    asm volatile(
        "mma.sync.aligned.m16n8k8.row.col.f32.tf32.tf32.f32 "
        "{%0,%1,%2,%3}, {%4,%5,%6,%7}, {%8,%9}, {%0,%1,%2,%3};\n"
        : "+f"(c[0]), "+f"(c[1]), "+f"(c[2]), "+f"(c[3])
        : "r"(a[0]), "r"(a[1]), "r"(a[2]), "r"(a[3]),
          "r"(b[0]), "r"(b[1]));
}
__device__ __forceinline__ void cp_async16(uint32_t saddr, const void* g) {
    asm volatile("cp.async.cg.shared.global [%0], [%1], 16;\n" :: "r"(saddr), "l"(g));
}
__device__ __forceinline__ void cp_commit() {
    asm volatile("cp.async.commit_group;\n" ::);
}
__device__ __forceinline__ void cp_wait1() {
    asm volatile("cp.async.wait_group 1;\n" ::);
}

// ---------------------------------------------------------------------------
// Pre-pass: round Q,K,V inputs and the 4 weight matrices to canonical tf32.
// grid (8192, 7), 256 threads, one float4 per thread (weights guard idx).
// ---------------------------------------------------------------------------
__global__ __launch_bounds__(256) void round_pre(
    const float* __restrict__ Q, const float* __restrict__ K, const float* __restrict__ V,
    const float* __restrict__ W0, const float* __restrict__ W1,
    const float* __restrict__ W2, const float* __restrict__ W3,
    float* __restrict__ rq, float* __restrict__ rk, float* __restrict__ rv,
    float* __restrict__ rw)
{
    const int z = blockIdx.y;
    const float4* src;
    float4* dst;
    int n;
    if (z == 0)      { src = (const float4*)Q;  dst = (float4*)rq; n = MROWS * EMB / 4; }
    else if (z == 1) { src = (const float4*)K;  dst = (float4*)rk; n = MROWS * EMB / 4; }
    else if (z == 2) { src = (const float4*)V;  dst = (float4*)rv; n = MROWS * EMB / 4; }
    else {
        const float* w = (z == 3) ? W0 : (z == 4) ? W1 : (z == 5) ? W2 : W3;
        src = (const float4*)w;
        dst = (float4*)(rw + (size_t)(z - 3) * EMB * EMB);
        n = EMB * EMB / 4;
    }
    int i = blockIdx.x * 256 + threadIdx.x;
    if (i < n) dst[i] = tf32x4(src[i]);
}

// ---------------------------------------------------------------------------
// TF32 tensor-core GEMM, cp.async 3-stage pipeline, z-batched over up to 3
// independent problems. Inputs MUST be pre-rounded tf32 (HW truncation in
// mma is then the identity -> numerics identical to cvt.rna-at-STS).
// BM=128, BN=128, BK=32, 128 threads (4 warps), warp tile 64x64, m16n8k8.
// Smem: 3 stages x (As[128][36] + Bs[32][136]) = 107520 B -> 2 CTAs/SM.
// roundC: round outputs to tf32 (for q/k/v feeding flash).
// ---------------------------------------------------------------------------
#define GSTAGES 3
#define ASE (128 * 36)
#define BSE (32 * 136)
#define GEMM_SMEM_BYTES (GSTAGES * (ASE + BSE) * 4)   // 107520

__global__ __launch_bounds__(128, 2) void gemm_tc3(
    const float* __restrict__ A0, const float* __restrict__ A1, const float* __restrict__ A2,
    const float* __restrict__ W0, const float* __restrict__ W1, const float* __restrict__ W2,
    const float* __restrict__ b0, const float* __restrict__ b1, const float* __restrict__ b2,
    float* __restrict__ C0, float* __restrict__ C1, float* __restrict__ C2,
    int M, int N, int K, int roundC)
{
    extern __shared__ float smg[];

    const int z = blockIdx.z;
    const float* A    = (z == 0) ? A0 : (z == 1) ? A1 : A2;
    const float* W    = (z == 0) ? W0 : (z == 1) ? W1 : W2;
    const float* bias = (z == 0) ? b0 : (z == 1) ? b1 : b2;
    float*       C    = (z == 0) ? C0 : (z == 1) ? C1 : C2;

    const int tid  = threadIdx.x;
    const int lane = tid & 31;
    const int wid  = tid >> 5;      // 0..3
    const int wm   = wid >> 1;      // 2 warps along M (64 each)
    const int wn   = wid & 1;       // 2 warps along N (64 each)
    const int bm   = blockIdx.y;
    const int bn   = blockIdx.x;
    const int grp  = lane >> 2;
    const int tig  = lane & 3;

    const float* Abase = A + (size_t)(bm * 128) * K;
    const float* Wbase = W + bn * 128;
    const uint32_t sbase = (uint32_t)__cvta_generic_to_shared(smg);

    float acc[4][8][4];
    #pragma unroll
    for (int i = 0; i < 4; i++)
        #pragma unroll
        for (int j = 0; j < 8; j++)
            #pragma unroll
            for (int q = 0; q < 4; q++) acc[i][j][q] = 0.f;

    // async stage loader: A 8x16B + B 8x16B per thread
    auto issue_stage = [&](int s, int k0) {
        #pragma unroll
        for (int i = 0; i < 8; i++) {
            int idx = tid + 128 * i;
            int r = idx >> 3, c = (idx & 7) << 2;
            uint32_t dst = sbase + (uint32_t)((s * ASE + r * 36 + c) * 4);
            cp_async16(dst, Abase + (size_t)r * K + k0 + c);
        }
        #pragma unroll
        for (int i = 0; i < 8; i++) {
            int idx = tid + 128 * i;
            int r = idx >> 5, c = (idx & 31) << 2;
            uint32_t dst = sbase + (uint32_t)((GSTAGES * ASE + s * BSE + r * 136 + c) * 4);
            cp_async16(dst, Wbase + (size_t)(k0 + r) * N + c);
        }
    };

    issue_stage(0, 0);  cp_commit();
    issue_stage(1, 32); cp_commit();

    int s = 0;
    for (int k0 = 0; k0 < K; k0 += 32) {
        cp_wait1();          // stage s complete (2 groups max in flight)
        __syncthreads();     // make it visible to all warps

        if (k0 + 64 < K) issue_stage((s + 2) % 3, k0 + 64);
        cp_commit();         // commit (possibly empty) to keep group counts uniform

        const float* aS = smg + s * ASE;
        const float* bS = smg + GSTAGES * ASE + s * BSE;

        #pragma unroll
        for (int ks = 0; ks < 4; ks++) {
            const int kb = ks * 8;
            uint32_t af[4][4];
            #pragma unroll
            for (int mf = 0; mf < 4; mf++) {
                const float* p0 = aS + (wm * 64 + mf * 16 + grp) * 36 + kb + tig;
                const float* p1 = p0 + 8 * 36;
                af[mf][0] = __float_as_uint(p0[0]);
                af[mf][1] = __float_as_uint(p1[0]);
                af[mf][2] = __float_as_uint(p0[4]);
                af[mf][3] = __float_as_uint(p1[4]);
            }
            uint32_t bf[8][2];
            #pragma unroll
            for (int nf = 0; nf < 8; nf++) {
                const float* q0 = bS + (kb + tig) * 136 + wn * 64 + nf * 8 + grp;
                bf[nf][0] = __float_as_uint(q0[0]);
                bf[nf][1] = __float_as_uint(q0[4 * 136]);
            }
            #pragma unroll
            for (int mf = 0; mf < 4; mf++)
                #pragma unroll
                for (int nf = 0; nf < 8; nf++)
                    mma_tf32(acc[mf][nf], af[mf], bf[nf]);
        }
        s = (s + 1) % 3;
    }

    // epilogue: bias (+ optional tf32 rounding), float2 stores
    float2 bb[8];
    #pragma unroll
    for (int nf = 0; nf < 8; nf++)
        bb[nf] = *(const float2*)(bias + bn * 128 + wn * 64 + nf * 8 + tig * 2);

    #pragma unroll
    for (int mf = 0; mf < 4; mf++) {
        int row0 = bm * 128 + wm * 64 + mf * 16 + grp;
        #pragma unroll
        for (int nf = 0; nf < 8; nf++) {
            int col = bn * 128 + wn * 64 + nf * 8 + tig * 2;
            float2 v0, v1;
            v0.x = acc[mf][nf][0] + bb[nf].x;
            v0.y = acc[mf][nf][1] + bb[nf].y;
            v1.x = acc[mf][nf][2] + bb[nf].x;
            v1.y = acc[mf][nf][3] + bb[nf].y;
            if (roundC) {
                v0.x = to_tf32(v0.x); v0.y = to_tf32(v0.y);
                v1.x = to_tf32(v1.x); v1.y = to_tf32(v1.y);
            }
            *(float2*)(C + (size_t)row0 * N + col)       = v0;
            *(float2*)(C + (size_t)(row0 + 8) * N + col) = v1;
        }
    }
}

// ---------------------------------------------------------------------------
// Tensor-core causal flash attention (TF32 mma, FA2-style).
// BM=64, 128 threads (4 warps x 16 query rows), 3 CTAs/SM.
// Inputs g_q/g_k/g_v are pre-rounded tf32 by the GEMM epilogue -> staging
// needs no cvt. Output is rounded to tf32 for the out-projection GEMM.
// ---------------------------------------------------------------------------
#define BM 64
#define PS_STRIDE 68
#define KS_STRIDE 68
#define VS_STRIDE 72
#define OFF_KS (BM * PS_STRIDE)
#define OFF_VS (OFF_KS + 64 * KS_STRIDE)
#define SMEM_FLASH_BYTES ((OFF_VS + 64 * VS_STRIDE) * 4)   // 53248

__global__ __launch_bounds__(128, 3) void flash_tc(
    const float* __restrict__ Qp, const float* __restrict__ Kp,
    const float* __restrict__ Vp, float* __restrict__ Op)
{
    extern __shared__ float sm[];
    float* Ps = sm;
    float* Ks = sm + OFF_KS;
    float* Vs = sm + OFF_VS;

    const int bh = blockIdx.y;
    const int b  = bh >> 4, h = bh & 15;
    const int m0 = blockIdx.x * BM;
    const int t  = threadIdx.x, lane = t & 31, w = t >> 5;   // w: 0..3
    const int grp = lane >> 2, tig = lane & 3;

    const float* Qbase = Qp + (size_t)b * SEQ * EMB + h * HDIM;
    const float* Kbase = Kp + (size_t)b * SEQ * EMB + h * HDIM;
    const float* Vbase = Vp + (size_t)b * SEQ * EMB + h * HDIM;

    // Stage Q tile (rows m0..m0+63) into Ps (already tf32-rounded).
    #pragma unroll
    for (int i = 0; i < 8; i++) {
        int idx = t + i * 128;
        int r = idx >> 4, c4 = idx & 15;
        *(float4*)(Ps + r * PS_STRIDE + c4 * 4) =
            *(const float4*)(Qbase + (size_t)(m0 + r) * EMB + c4 * 4);
    }
    __syncthreads();

    // Persistent Q a-fragments (m16k8 x 8 k-steps).
    const int qr = w * 16 + grp;
    uint32_t qf[8][4];
    #pragma unroll
    for (int kf = 0; kf < 8; kf++) {
        const float* p0 = Ps + qr * PS_STRIDE + kf * 8 + tig;
        const float* p1 = p0 + 8 * PS_STRIDE;
        qf[kf][0] = __float_as_uint(p0[0]);
        qf[kf][1] = __float_as_uint(p1[0]);
        qf[kf][2] = __float_as_uint(p0[4]);
        qf[kf][3] = __float_as_uint(p1[4]);
    }

    float of[8][4];
    #pragma unroll
    for (int nf = 0; nf < 8; nf++)
        #pragma unroll
        for (int q = 0; q < 4; q++) of[nf][q] = 0.f;
    float mm0 = -INFINITY, mm1 = -INFINITY, ll0 = 0.f, ll1 = 0.f;

    const int rowMin = m0 + w * 16;
    const int rowMax = rowMin + 15;
    const int i0 = rowMin + grp;   // global row of c0/c1
    const int i1 = i0 + 8;         // global row of c2/c3

    for (int n0 = 0; n0 < m0 + BM; n0 += 64) {
        __syncthreads();   // Ks/Vs reuse
        #pragma unroll
        for (int i = 0; i < 8; i++) {
            int idx = t + i * 128;
            int r = idx >> 4, c4 = idx & 15;
            *(float4*)(Ks + r * KS_STRIDE + c4 * 4) =
                *(const float4*)(Kbase + (size_t)(n0 + r) * EMB + c4 * 4);
            *(float4*)(Vs + r * VS_STRIDE + c4 * 4) =
                *(const float4*)(Vbase + (size_t)(n0 + r) * EMB + c4 * 4);
        }
        __syncthreads();

        if (n0 > rowMax) continue;   // warp-uniform skip (still hits syncs)

        // --- S = Q @ K^T ---
        float sf[8][4];
        #pragma unroll
        for (int nf = 0; nf < 8; nf++)
            #pragma unroll
            for (int q = 0; q < 4; q++) sf[nf][q] = 0.f;

        #pragma unroll
        for (int nf = 0; nf < 8; nf++) {
            const float* kb = Ks + (nf * 8 + grp) * KS_STRIDE + tig;
            #pragma unroll
            for (int kf = 0; kf < 8; kf++) {
                uint32_t bfr[2];
                bfr[0] = __float_as_uint(kb[kf * 8]);
                bfr[1] = __float_as_uint(kb[kf * 8 + 4]);
                mma_tf32(sf[nf], qf[kf], bfr);
            }
        }

        // --- scale (log2 space) + causal mask ---
        const bool fullT = (n0 + 63 <= rowMin);
        #pragma unroll
        for (int nf = 0; nf < 8; nf++) {
            #pragma unroll
            for (int q = 0; q < 4; q++) sf[nf][q] *= SLOG2;
            if (!fullT) {
                int j0 = n0 + nf * 8 + 2 * tig;
                if (j0     > i0) sf[nf][0] = -INFINITY;
                if (j0 + 1 > i0) sf[nf][1] = -INFINITY;
                if (j0     > i1) sf[nf][2] = -INFINITY;
                if (j0 + 1 > i1) sf[nf][3] = -INFINITY;
            }
        }

        // --- online softmax (rows live in 4 consecutive lanes) ---
        float mx0 = -INFINITY, mx1 = -INFINITY;
        #pragma unroll
        for (int nf = 0; nf < 8; nf++) {
            mx0 = fmaxf(mx0, fmaxf(sf[nf][0], sf[nf][1]));
            mx1 = fmaxf(mx1, fmaxf(sf[nf][2], sf[nf][3]));
        }
        mx0 = fmaxf(mx0, __shfl_xor_sync(0xffffffffu, mx0, 1));
        mx0 = fmaxf(mx0, __shfl_xor_sync(0xffffffffu, mx0, 2));
        mx1 = fmaxf(mx1, __shfl_xor_sync(0xffffffffu, mx1, 1));
        mx1 = fmaxf(mx1, __shfl_xor_sync(0xffffffffu, mx1, 2));

        float nm0 = fmaxf(mm0, mx0), nm1 = fmaxf(mm1, mx1);
        float c0 = fast_exp2(mm0 - nm0), c1 = fast_exp2(mm1 - nm1);
        mm0 = nm0; mm1 = nm1;

        float s0 = 0.f, s1 = 0.f;
        float* pr0 = Ps + qr * PS_STRIDE + 2 * tig;
        float* pr1 = pr0 + 8 * PS_STRIDE;
        #pragma unroll
        for (int nf = 0; nf < 8; nf++) {
            // round P to tf32; denominator accumulates the SAME rounded values
            float p00 = to_tf32(fast_exp2(sf[nf][0] - nm0));
            float p01 = to_tf32(fast_exp2(sf[nf][1] - nm0));
            float p10 = to_tf32(fast_exp2(sf[nf][2] - nm1));
            float p11 = to_tf32(fast_exp2(sf[nf][3] - nm1));
            s0 += p00 + p01;
            s1 += p10 + p11;
            *(float2*)(pr0 + nf * 8) = make_float2(p00, p01);
            *(float2*)(pr1 + nf * 8) = make_float2(p10, p11);
            of[nf][0] *= c0; of[nf][1] *= c0;
            of[nf][2] *= c1; of[nf][3] *= c1;
        }
        // reduce partial denominators across the 4 lanes of each row
        s0 += __shfl_xor_sync(0xffffffffu, s0, 1);
        s0 += __shfl_xor_sync(0xffffffffu, s0, 2);
        s1 += __shfl_xor_sync(0xffffffffu, s1, 1);
        s1 += __shfl_xor_sync(0xffffffffu, s1, 2);
        ll0 = ll0 * c0 + s0;
        ll1 = ll1 * c1 + s1;
        __syncwarp();   // P rows are warp-private

        // --- O += P @ V ---
        uint32_t af[8][4];
        #pragma unroll
        for (int kf = 0; kf < 8; kf++) {
            const float* a0 = Ps + qr * PS_STRIDE + kf * 8 + tig;
            const float* a1 = a0 + 8 * PS_STRIDE;
            af[kf][0] = __float_as_uint(a0[0]);
            af[kf][1] = __float_as_uint(a1[0]);
            af[kf][2] = __float_as_uint(a0[4]);
            af[kf][3] = __float_as_uint(a1[4]);
        }
        #pragma unroll
        for (int nf = 0; nf < 8; nf++) {
            #pragma unroll
            for (int kf = 0; kf < 8; kf++) {
                uint32_t bfr[2];
                const float* vb = Vs + (kf * 8 + tig) * VS_STRIDE + nf * 8 + grp;
                bfr[0] = __float_as_uint(vb[0]);
                bfr[1] = __float_as_uint(vb[4 * VS_STRIDE]);
                mma_tf32(of[nf], af[kf], bfr);
            }
        }
    }

    // --- epilogue: normalize, round to tf32 (feeds out-projection), store ---
    const float inv0 = 1.f / ll0;
    const float inv1 = 1.f / ll1;
    float* O0 = Op + (size_t)(b * SEQ + m0 + w * 16 + grp) * EMB + h * HDIM + 2 * tig;
    float* O1 = O0 + (size_t)8 * EMB;
    #pragma unroll
    for (int nf = 0; nf < 8; nf++) {
        *(float2*)(O0 + nf * 8) = make_float2(to_tf32(of[nf][0] * inv0),
                                              to_tf32(of[nf][1] * inv0));
        *(float2*)(O1 + nf * 8) = make_float2(to_tf32(of[nf][2] * inv1),
                                              to_tf32(of[nf][3] * inv1));
    }
}

// ---------------------------------------------------------------------------
// Launch
// ---------------------------------------------------------------------------
extern "C" void kernel_launch(void* const* d_in, const int* in_sizes, int n_in,
                              void* d_out, int out_size)
{
    const float* Q  = (const float*)d_in[0];
    const float* K  = (const float*)d_in[1];
    const float* V  = (const float*)d_in[2];
    const float* WQ = (const float*)d_in[3];
    const float* bQ = (const float*)d_in[4];
    const float* WK = (const float*)d_in[5];
    const float* bK = (const float*)d_in[6];
    const float* WV = (const float*)d_in[7];
    const float* bV = (const float*)d_in[8];
    const float* WO = (const float*)d_in[9];
    const float* bO = (const float*)d_in[10];
    float* out = (float*)d_out;

    float *gq, *gk, *gv, *ga, *grq, *grk, *grv, *gw;
    cudaGetSymbolAddress((void**)&gq,  g_q);
    cudaGetSymbolAddress((void**)&gk,  g_k);
    cudaGetSymbolAddress((void**)&gv,  g_v);
    cudaGetSymbolAddress((void**)&ga,  g_att);
    cudaGetSymbolAddress((void**)&grq, g_rq);
    cudaGetSymbolAddress((void**)&grk, g_rk);
    cudaGetSymbolAddress((void**)&grv, g_rv);
    cudaGetSymbolAddress((void**)&gw,  g_w);

    cudaFuncSetAttribute(gemm_tc3, cudaFuncAttributeMaxDynamicSharedMemorySize,
                         GEMM_SMEM_BYTES);
    cudaFuncSetAttribute(flash_tc, cudaFuncAttributeMaxDynamicSharedMemorySize,
                         SMEM_FLASH_BYTES);

    // Pre-round inputs + weights to canonical tf32
    round_pre<<<dim3(8192, 7), 256>>>(Q, K, V, WQ, WK, WV, WO,
                                      grq, grk, grv, gw);

    // Fused Q/K/V projections (outputs rounded to tf32 for flash)
    dim3 gqkv(EMB / 128, MROWS / 128, 3);  // (8, 64, 3)
    gemm_tc3<<<gqkv, 128, GEMM_SMEM_BYTES>>>(
        grq, grk, grv,
        gw, gw + (size_t)EMB * EMB, gw + (size_t)2 * EMB * EMB,
        bQ, bK, bV, gq, gk, gv, MROWS, EMB, EMB, 1);

    dim3 fg(SEQ / BM, BATCH * HEADS);      // (32, 64)
    flash_tc<<<fg, 128, SMEM_FLASH_BYTES>>>(gq, gk, gv, ga);

    // Output projection (fp32 output, no rounding)
    dim3 go(EMB / 128, MROWS / 128, 1);
    const float* gwo = gw + (size_t)3 * EMB * EMB;
    gemm_tc3<<<go, 128, GEMM_SMEM_BYTES>>>(
        ga, ga, ga, gwo, gwo, gwo, bO, bO, bO,
        out, out, out, MROWS, EMB, EMB, 0);
}

// round 12
// speedup vs baseline: 4.2909x; 1.0055x over previous
#include <cuda_runtime.h>
#include <cuda_bf16.h>
#include <math.h>
#include <stdint.h>

// Problem constants
#define BATCH 4
#define SEQ   2048
#define EMB   1024
#define HEADS 16
#define HDIM  64
#define MROWS (BATCH * SEQ)          // 8192
#define ATT_SCALE 0.125f             // 1/sqrt(64)
#define SLOG2 (0.125f * 1.4426950408889634f)   // scale * log2(e)

// Scratch buffers (device globals: allocation-free per harness rules)
__device__ float g_q[MROWS * EMB];
__device__ float g_k[MROWS * EMB];
__device__ float g_v[MROWS * EMB];
__device__ float g_att[MROWS * EMB];
// tf32-pre-rounded operands (bitwise-identical numerics vs cvt-at-STS)
__device__ float g_rq[MROWS * EMB];
__device__ float g_rk[MROWS * EMB];
__device__ float g_rv[MROWS * EMB];
__device__ float g_w[4 * EMB * EMB];

// ---------------------------------------------------------------------------
// TF32 helpers
// ---------------------------------------------------------------------------
__device__ __forceinline__ float to_tf32(float x) {
    uint32_t u;
    asm("cvt.rna.tf32.f32 %0, %1;" : "=r"(u) : "f"(x));
    return __uint_as_float(u);
}
__device__ __forceinline__ float4 tf32x4(float4 v) {
    v.x = to_tf32(v.x); v.y = to_tf32(v.y);
    v.z = to_tf32(v.z); v.w = to_tf32(v.w);
    return v;
}
__device__ __forceinline__ float fast_exp2(float x) {
    float y;
    asm("ex2.approx.f32 %0, %1;" : "=f"(y) : "f"(x));
    return y;
}
__device__ __forceinline__ void mma_tf32(float* c, const uint32_t* a, const uint32_t* b) {
    asm volatile(
        "mma.sync.aligned.m16n8k8.row.col.f32.tf32.tf32.f32 "
        "{%0,%1,%2,%3}, {%4,%5,%6,%7}, {%8,%9}, {%0,%1,%2,%3};\n"
        : "+f"(c[0]), "+f"(c[1]), "+f"(c[2]), "+f"(c[3])
        : "r"(a[0]), "r"(a[1]), "r"(a[2]), "r"(a[3]),
          "r"(b[0]), "r"(b[1]));
}
__device__ __forceinline__ void cp_async16(uint32_t saddr, const void* g) {
    asm volatile("cp.async.cg.shared.global [%0], [%1], 16;\n" :: "r"(saddr), "l"(g));
}
__device__ __forceinline__ void cp_commit() {
    asm volatile("cp.async.commit_group;\n" ::);
}
__device__ __forceinline__ void cp_wait1() {
    asm volatile("cp.async.wait_group 1;\n" ::);
}
__device__ __forceinline__ void cp_wait0() {
    asm volatile("cp.async.wait_group 0;\n" ::);
}

// ---------------------------------------------------------------------------
// Pre-pass: round Q,K,V inputs and the 4 weight matrices to canonical tf32.
// ---------------------------------------------------------------------------
__global__ __launch_bounds__(256) void round_pre(
    const float* __restrict__ Q, const float* __restrict__ K, const float* __restrict__ V,
    const float* __restrict__ W0, const float* __restrict__ W1,
    const float* __restrict__ W2, const float* __restrict__ W3,
    float* __restrict__ rq, float* __restrict__ rk, float* __restrict__ rv,
    float* __restrict__ rw)
{
    const int z = blockIdx.y;
    const float4* src;
    float4* dst;
    int n;
    if (z == 0)      { src = (const float4*)Q;  dst = (float4*)rq; n = MROWS * EMB / 4; }
    else if (z == 1) { src = (const float4*)K;  dst = (float4*)rk; n = MROWS * EMB / 4; }
    else if (z == 2) { src = (const float4*)V;  dst = (float4*)rv; n = MROWS * EMB / 4; }
    else {
        const float* w = (z == 3) ? W0 : (z == 4) ? W1 : (z == 5) ? W2 : W3;
        src = (const float4*)w;
        dst = (float4*)(rw + (size_t)(z - 3) * EMB * EMB);
        n = EMB * EMB / 4;
    }
    int i = blockIdx.x * 256 + threadIdx.x;
    if (i < n) dst[i] = tf32x4(src[i]);
}

// ---------------------------------------------------------------------------
// TF32 tensor-core GEMM, cp.async 3-stage pipeline, z-batched over up to 3
// independent problems. Inputs MUST be pre-rounded tf32.
// 256 threads (8 warps), warp tile 64x32, BM=128, BN=128, BK=32, m16n8k8.
// 2 CTAs/SM by smem = 16 warps/SM (4/SMSP).
// Smem: 3 stages x (As[128][36] + Bs[32][136]) = 107520 B.
// !! Must be launched with exactly 256 threads (R11 failed: out-proj launch
//    still said 128 -> half-loaded tiles + half-missing warps).
// ---------------------------------------------------------------------------
#define GSTAGES 3
#define ASE (128 * 36)
#define BSE (32 * 136)
#define GEMM_SMEM_BYTES (GSTAGES * (ASE + BSE) * 4)   // 107520

__global__ __launch_bounds__(256, 2) void gemm_tc3(
    const float* __restrict__ A0, const float* __restrict__ A1, const float* __restrict__ A2,
    const float* __restrict__ W0, const float* __restrict__ W1, const float* __restrict__ W2,
    const float* __restrict__ b0, const float* __restrict__ b1, const float* __restrict__ b2,
    float* __restrict__ C0, float* __restrict__ C1, float* __restrict__ C2,
    int M, int N, int K, int roundC)
{
    extern __shared__ float smg[];

    const int z = blockIdx.z;
    const float* A    = (z == 0) ? A0 : (z == 1) ? A1 : A2;
    const float* W    = (z == 0) ? W0 : (z == 1) ? W1 : W2;
    const float* bias = (z == 0) ? b0 : (z == 1) ? b1 : b2;
    float*       C    = (z == 0) ? C0 : (z == 1) ? C1 : C2;

    const int tid  = threadIdx.x;
    const int lane = tid & 31;
    const int wid  = tid >> 5;      // 0..7
    const int wm   = wid & 1;       // 2 warps along M (64 each)
    const int wn   = wid >> 1;      // 4 warps along N (32 each)
    const int bm   = blockIdx.y;
    const int bn   = blockIdx.x;
    const int grp  = lane >> 2;
    const int tig  = lane & 3;

    const float* Abase = A + (size_t)(bm * 128) * K;
    const float* Wbase = W + bn * 128;
    const uint32_t sbase = (uint32_t)__cvta_generic_to_shared(smg);

    float acc[4][4][4];
    #pragma unroll
    for (int i = 0; i < 4; i++)
        #pragma unroll
        for (int j = 0; j < 4; j++)
            #pragma unroll
            for (int q = 0; q < 4; q++) acc[i][j][q] = 0.f;

    // async stage loader: A 4x16B + B 4x16B per thread (256 threads)
    auto issue_stage = [&](int s, int k0) {
        #pragma unroll
        for (int i = 0; i < 4; i++) {
            int idx = tid + 256 * i;
            int r = idx >> 3, c = (idx & 7) << 2;
            uint32_t dst = sbase + (uint32_t)((s * ASE + r * 36 + c) * 4);
            cp_async16(dst, Abase + (size_t)r * K + k0 + c);
        }
        #pragma unroll
        for (int i = 0; i < 4; i++) {
            int idx = tid + 256 * i;
            int r = idx >> 5, c = (idx & 31) << 2;
            uint32_t dst = sbase + (uint32_t)((GSTAGES * ASE + s * BSE + r * 136 + c) * 4);
            cp_async16(dst, Wbase + (size_t)(k0 + r) * N + c);
        }
    };

    issue_stage(0, 0);  cp_commit();
    issue_stage(1, 32); cp_commit();

    int s = 0;
    for (int k0 = 0; k0 < K; k0 += 32) {
        cp_wait1();          // stage s complete (2 groups max in flight)
        __syncthreads();     // make it visible to all warps

        if (k0 + 64 < K) issue_stage((s + 2) % 3, k0 + 64);
        cp_commit();         // commit (possibly empty) to keep group counts uniform

        const float* aS = smg + s * ASE;
        const float* bS = smg + GSTAGES * ASE + s * BSE;

        #pragma unroll
        for (int ks = 0; ks < 4; ks++) {
            const int kb = ks * 8;
            uint32_t af[4][4];
            #pragma unroll
            for (int mf = 0; mf < 4; mf++) {
                const float* p0 = aS + (wm * 64 + mf * 16 + grp) * 36 + kb + tig;
                const float* p1 = p0 + 8 * 36;
                af[mf][0] = __float_as_uint(p0[0]);
                af[mf][1] = __float_as_uint(p1[0]);
                af[mf][2] = __float_as_uint(p0[4]);
                af[mf][3] = __float_as_uint(p1[4]);
            }
            uint32_t bf[4][2];
            #pragma unroll
            for (int nf = 0; nf < 4; nf++) {
                const float* q0 = bS + (kb + tig) * 136 + wn * 32 + nf * 8 + grp;
                bf[nf][0] = __float_as_uint(q0[0]);
                bf[nf][1] = __float_as_uint(q0[4 * 136]);
            }
            #pragma unroll
            for (int mf = 0; mf < 4; mf++)
                #pragma unroll
                for (int nf = 0; nf < 4; nf++)
                    mma_tf32(acc[mf][nf], af[mf], bf[nf]);
        }
        s = (s + 1) % 3;
    }

    // epilogue: bias (+ optional tf32 rounding), float2 stores
    float2 bb[4];
    #pragma unroll
    for (int nf = 0; nf < 4; nf++)
        bb[nf] = *(const float2*)(bias + bn * 128 + wn * 32 + nf * 8 + tig * 2);

    #pragma unroll
    for (int mf = 0; mf < 4; mf++) {
        int row0 = bm * 128 + wm * 64 + mf * 16 + grp;
        #pragma unroll
        for (int nf = 0; nf < 4; nf++) {
            int col = bn * 128 + wn * 32 + nf * 8 + tig * 2;
            float2 v0, v1;
            v0.x = acc[mf][nf][0] + bb[nf].x;
            v0.y = acc[mf][nf][1] + bb[nf].y;
            v1.x = acc[mf][nf][2] + bb[nf].x;
            v1.y = acc[mf][nf][3] + bb[nf].y;
            if (roundC) {
                v0.x = to_tf32(v0.x); v0.y = to_tf32(v0.y);
                v1.x = to_tf32(v1.x); v1.y = to_tf32(v1.y);
            }
            *(float2*)(C + (size_t)row0 * N + col)       = v0;
            *(float2*)(C + (size_t)(row0 + 8) * N + col) = v1;
        }
    }
}

// ---------------------------------------------------------------------------
// Tensor-core causal flash attention (TF32 mma, FA2-style).
// BM=64, 128 threads (4 warps x 16 query rows), 3 CTAs/SM.
// K/V tile loads via cp.async (inputs pre-rounded tf32 -> no cvt).
// ---------------------------------------------------------------------------
#define BM 64
#define PS_STRIDE 68
#define KS_STRIDE 68
#define VS_STRIDE 72
#define OFF_KS (BM * PS_STRIDE)
#define OFF_VS (OFF_KS + 64 * KS_STRIDE)
#define SMEM_FLASH_BYTES ((OFF_VS + 64 * VS_STRIDE) * 4)   // 53248

__global__ __launch_bounds__(128, 3) void flash_tc(
    const float* __restrict__ Qp, const float* __restrict__ Kp,
    const float* __restrict__ Vp, float* __restrict__ Op)
{
    extern __shared__ float sm[];
    float* Ps = sm;
    float* Ks = sm + OFF_KS;
    float* Vs = sm + OFF_VS;

    const int bh = blockIdx.y;
    const int b  = bh >> 4, h = bh & 15;
    const int m0 = blockIdx.x * BM;
    const int t  = threadIdx.x, lane = t & 31, w = t >> 5;   // w: 0..3
    const int grp = lane >> 2, tig = lane & 3;

    const float* Qbase = Qp + (size_t)b * SEQ * EMB + h * HDIM;
    const float* Kbase = Kp + (size_t)b * SEQ * EMB + h * HDIM;
    const float* Vbase = Vp + (size_t)b * SEQ * EMB + h * HDIM;
    const uint32_t sKs = (uint32_t)__cvta_generic_to_shared(Ks);
    const uint32_t sVs = (uint32_t)__cvta_generic_to_shared(Vs);

    // Stage Q tile (rows m0..m0+63) into Ps (already tf32-rounded).
    #pragma unroll
    for (int i = 0; i < 8; i++) {
        int idx = t + i * 128;
        int r = idx >> 4, c4 = idx & 15;
        *(float4*)(Ps + r * PS_STRIDE + c4 * 4) =
            *(const float4*)(Qbase + (size_t)(m0 + r) * EMB + c4 * 4);
    }
    __syncthreads();

    // Persistent Q a-fragments (m16k8 x 8 k-steps).
    const int qr = w * 16 + grp;
    uint32_t qf[8][4];
    #pragma unroll
    for (int kf = 0; kf < 8; kf++) {
        const float* p0 = Ps + qr * PS_STRIDE + kf * 8 + tig;
        const float* p1 = p0 + 8 * PS_STRIDE;
        qf[kf][0] = __float_as_uint(p0[0]);
        qf[kf][1] = __float_as_uint(p1[0]);
        qf[kf][2] = __float_as_uint(p0[4]);
        qf[kf][3] = __float_as_uint(p1[4]);
    }

    float of[8][4];
    #pragma unroll
    for (int nf = 0; nf < 8; nf++)
        #pragma unroll
        for (int q = 0; q < 4; q++) of[nf][q] = 0.f;
    float mm0 = -INFINITY, mm1 = -INFINITY, ll0 = 0.f, ll1 = 0.f;

    const int rowMin = m0 + w * 16;
    const int rowMax = rowMin + 15;
    const int i0 = rowMin + grp;   // global row of c0/c1
    const int i1 = i0 + 8;         // global row of c2/c3

    for (int n0 = 0; n0 < m0 + BM; n0 += 64) {
        __syncthreads();   // Ks/Vs reuse
        // KV tile load via cp.async: 16 x 16B per thread
        #pragma unroll
        for (int i = 0; i < 8; i++) {
            int idx = t + i * 128;
            int r = idx >> 4, c4 = idx & 15;
            cp_async16(sKs + (uint32_t)((r * KS_STRIDE + c4 * 4) * 4),
                       Kbase + (size_t)(n0 + r) * EMB + c4 * 4);
            cp_async16(sVs + (uint32_t)((r * VS_STRIDE + c4 * 4) * 4),
                       Vbase + (size_t)(n0 + r) * EMB + c4 * 4);
        }
        cp_commit();
        cp_wait0();
        __syncthreads();

        if (n0 > rowMax) continue;   // warp-uniform skip (still hits syncs)

        // --- S = Q @ K^T ---
        float sf[8][4];
        #pragma unroll
        for (int nf = 0; nf < 8; nf++)
            #pragma unroll
            for (int q = 0; q < 4; q++) sf[nf][q] = 0.f;

        #pragma unroll
        for (int nf = 0; nf < 8; nf++) {
            const float* kb = Ks + (nf * 8 + grp) * KS_STRIDE + tig;
            #pragma unroll
            for (int kf = 0; kf < 8; kf++) {
                uint32_t bfr[2];
                bfr[0] = __float_as_uint(kb[kf * 8]);
                bfr[1] = __float_as_uint(kb[kf * 8 + 4]);
                mma_tf32(sf[nf], qf[kf], bfr);
            }
        }

        // --- scale (log2 space) + causal mask ---
        const bool fullT = (n0 + 63 <= rowMin);
        #pragma unroll
        for (int nf = 0; nf < 8; nf++) {
            #pragma unroll
            for (int q = 0; q < 4; q++) sf[nf][q] *= SLOG2;
            if (!fullT) {
                int j0 = n0 + nf * 8 + 2 * tig;
                if (j0     > i0) sf[nf][0] = -INFINITY;
                if (j0 + 1 > i0) sf[nf][1] = -INFINITY;
                if (j0     > i1) sf[nf][2] = -INFINITY;
                if (j0 + 1 > i1) sf[nf][3] = -INFINITY;
            }
        }

        // --- online softmax (rows live in 4 consecutive lanes) ---
        float mx0 = -INFINITY, mx1 = -INFINITY;
        #pragma unroll
        for (int nf = 0; nf < 8; nf++) {
            mx0 = fmaxf(mx0, fmaxf(sf[nf][0], sf[nf][1]));
            mx1 = fmaxf(mx1, fmaxf(sf[nf][2], sf[nf][3]));
        }
        mx0 = fmaxf(mx0, __shfl_xor_sync(0xffffffffu, mx0, 1));
        mx0 = fmaxf(mx0, __shfl_xor_sync(0xffffffffu, mx0, 2));
        mx1 = fmaxf(mx1, __shfl_xor_sync(0xffffffffu, mx1, 1));
        mx1 = fmaxf(mx1, __shfl_xor_sync(0xffffffffu, mx1, 2));

        float nm0 = fmaxf(mm0, mx0), nm1 = fmaxf(mm1, mx1);
        float c0 = fast_exp2(mm0 - nm0), c1 = fast_exp2(mm1 - nm1);
        mm0 = nm0; mm1 = nm1;

        float s0 = 0.f, s1 = 0.f;
        float* pr0 = Ps + qr * PS_STRIDE + 2 * tig;
        float* pr1 = pr0 + 8 * PS_STRIDE;
        #pragma unroll
        for (int nf = 0; nf < 8; nf++) {
            // round P to tf32; denominator accumulates the SAME rounded values
            float p00 = to_tf32(fast_exp2(sf[nf][0] - nm0));
            float p01 = to_tf32(fast_exp2(sf[nf][1] - nm0));
            float p10 = to_tf32(fast_exp2(sf[nf][2] - nm1));
            float p11 = to_tf32(fast_exp2(sf[nf][3] - nm1));
            s0 += p00 + p01;
            s1 += p10 + p11;
            *(float2*)(pr0 + nf * 8) = make_float2(p00, p01);
            *(float2*)(pr1 + nf * 8) = make_float2(p10, p11);
            of[nf][0] *= c0; of[nf][1] *= c0;
            of[nf][2] *= c1; of[nf][3] *= c1;
        }
        // reduce partial denominators across the 4 lanes of each row
        s0 += __shfl_xor_sync(0xffffffffu, s0, 1);
        s0 += __shfl_xor_sync(0xffffffffu, s0, 2);
        s1 += __shfl_xor_sync(0xffffffffu, s1, 1);
        s1 += __shfl_xor_sync(0xffffffffu, s1, 2);
        ll0 = ll0 * c0 + s0;
        ll1 = ll1 * c1 + s1;
        __syncwarp();   // P rows are warp-private

        // --- O += P @ V ---
        uint32_t af[8][4];
        #pragma unroll
        for (int kf = 0; kf < 8; kf++) {
            const float* a0 = Ps + qr * PS_STRIDE + kf * 8 + tig;
            const float* a1 = a0 + 8 * PS_STRIDE;
            af[kf][0] = __float_as_uint(a0[0]);
            af[kf][1] = __float_as_uint(a1[0]);
            af[kf][2] = __float_as_uint(a0[4]);
            af[kf][3] = __float_as_uint(a1[4]);
        }
        #pragma unroll
        for (int nf = 0; nf < 8; nf++) {
            #pragma unroll
            for (int kf = 0; kf < 8; kf++) {
                uint32_t bfr[2];
                const float* vb = Vs + (kf * 8 + tig) * VS_STRIDE + nf * 8 + grp;
                bfr[0] = __float_as_uint(vb[0]);
                bfr[1] = __float_as_uint(vb[4 * VS_STRIDE]);
                mma_tf32(of[nf], af[kf], bfr);
            }
        }
    }

    // --- epilogue: normalize, round to tf32 (feeds out-projection), store ---
    const float inv0 = 1.f / ll0;
    const float inv1 = 1.f / ll1;
    float* O0 = Op + (size_t)(b * SEQ + m0 + w * 16 + grp) * EMB + h * HDIM + 2 * tig;
    float* O1 = O0 + (size_t)8 * EMB;
    #pragma unroll
    for (int nf = 0; nf < 8; nf++) {
        *(float2*)(O0 + nf * 8) = make_float2(to_tf32(of[nf][0] * inv0),
                                              to_tf32(of[nf][1] * inv0));
        *(float2*)(O1 + nf * 8) = make_float2(to_tf32(of[nf][2] * inv1),
                                              to_tf32(of[nf][3] * inv1));
    }
}

// ---------------------------------------------------------------------------
// Launch
// ---------------------------------------------------------------------------
extern "C" void kernel_launch(void* const* d_in, const int* in_sizes, int n_in,
                              void* d_out, int out_size)
{
    const float* Q  = (const float*)d_in[0];
    const float* K  = (const float*)d_in[1];
    const float* V  = (const float*)d_in[2];
    const float* WQ = (const float*)d_in[3];
    const float* bQ = (const float*)d_in[4];
    const float* WK = (const float*)d_in[5];
    const float* bK = (const float*)d_in[6];
    const float* WV = (const float*)d_in[7];
    const float* bV = (const float*)d_in[8];
    const float* WO = (const float*)d_in[9];
    const float* bO = (const float*)d_in[10];
    float* out = (float*)d_out;

    float *gq, *gk, *gv, *ga, *grq, *grk, *grv, *gw;
    cudaGetSymbolAddress((void**)&gq,  g_q);
    cudaGetSymbolAddress((void**)&gk,  g_k);
    cudaGetSymbolAddress((void**)&gv,  g_v);
    cudaGetSymbolAddress((void**)&ga,  g_att);
    cudaGetSymbolAddress((void**)&grq, g_rq);
    cudaGetSymbolAddress((void**)&grk, g_rk);
    cudaGetSymbolAddress((void**)&grv, g_rv);
    cudaGetSymbolAddress((void**)&gw,  g_w);

    cudaFuncSetAttribute(gemm_tc3, cudaFuncAttributeMaxDynamicSharedMemorySize,
                         GEMM_SMEM_BYTES);
    cudaFuncSetAttribute(flash_tc, cudaFuncAttributeMaxDynamicSharedMemorySize,
                         SMEM_FLASH_BYTES);

    // Pre-round inputs + weights to canonical tf32
    round_pre<<<dim3(8192, 7), 256>>>(Q, K, V, WQ, WK, WV, WO,
                                      grq, grk, grv, gw);

    // Fused Q/K/V projections (outputs rounded to tf32 for flash)
    dim3 gqkv(EMB / 128, MROWS / 128, 3);  // (8, 64, 3)
    gemm_tc3<<<gqkv, 256, GEMM_SMEM_BYTES>>>(
        grq, grk, grv,
        gw, gw + (size_t)EMB * EMB, gw + (size_t)2 * EMB * EMB,
        bQ, bK, bV, gq, gk, gv, MROWS, EMB, EMB, 1);

    dim3 fg(SEQ / BM, BATCH * HEADS);      // (32, 64)
    flash_tc<<<fg, 128, SMEM_FLASH_BYTES>>>(gq, gk, gv, ga);

    // Output projection — FIXED: 256 threads (R11 regression: was 128)
    dim3 go(EMB / 128, MROWS / 128, 1);
    const float* gwo = gw + (size_t)3 * EMB * EMB;
    gemm_tc3<<<go, 256, GEMM_SMEM_BYTES>>>(
        ga, ga, ga, gwo, gwo, gwo, bO, bO, bO,
        out, out, out, MROWS, EMB, EMB, 0);
}

// round 15
// speedup vs baseline: 4.3795x; 1.0206x over previous
#include <cuda_runtime.h>
#include <cuda_bf16.h>
#include <math.h>
#include <stdint.h>

// Problem constants
#define BATCH 4
#define SEQ   2048
#define EMB   1024
#define HEADS 16
#define HDIM  64
#define MROWS (BATCH * SEQ)          // 8192
#define ATT_SCALE 0.125f             // 1/sqrt(64)
#define SLOG2 (0.125f * 1.4426950408889634f)   // scale * log2(e)

// NOTE (R13 lesson): this bench's PTX target is compute_103 (no 'a' suffix);
// ptxas rejects tcgen05.* there. mma.sync is the usable tensor path.

// Scratch buffers (device globals: allocation-free per harness rules)
__device__ float g_q[MROWS * EMB];
__device__ float g_k[MROWS * EMB];
__device__ float g_v[MROWS * EMB];
__device__ float g_att[MROWS * EMB];
// tf32-pre-rounded operands (bitwise-identical numerics vs cvt-at-STS)
__device__ float g_rq[MROWS * EMB];
__device__ float g_rk[MROWS * EMB];
__device__ float g_rv[MROWS * EMB];
__device__ float g_w[4 * EMB * EMB];

// ---------------------------------------------------------------------------
// TF32 helpers
// ---------------------------------------------------------------------------
__device__ __forceinline__ float to_tf32(float x) {
    uint32_t u;
    asm("cvt.rna.tf32.f32 %0, %1;" : "=r"(u) : "f"(x));
    return __uint_as_float(u);
}
__device__ __forceinline__ float4 tf32x4(float4 v) {
    v.x = to_tf32(v.x); v.y = to_tf32(v.y);
    v.z = to_tf32(v.z); v.w = to_tf32(v.w);
    return v;
}
__device__ __forceinline__ float fast_exp2(float x) {
    float y;
    asm("ex2.approx.f32 %0, %1;" : "=f"(y) : "f"(x));
    return y;
}
__device__ __forceinline__ void mma_tf32(float* c, const uint32_t* a, const uint32_t* b) {
    asm volatile(
        "mma.sync.aligned.m16n8k8.row.col.f32.tf32.tf32.f32 "
        "{%0,%1,%2,%3}, {%4,%5,%6,%7}, {%8,%9}, {%0,%1,%2,%3};\n"
        : "+f"(c[0]), "+f"(c[1]), "+f"(c[2]), "+f"(c[3])
        : "r"(a[0]), "r"(a[1]), "r"(a[2]), "r"(a[3]),
          "r"(b[0]), "r"(b[1]));
}
__device__ __forceinline__ void cp_async16(uint32_t saddr, const void* g) {
    asm volatile("cp.async.cg.shared.global [%0], [%1], 16;\n" :: "r"(saddr), "l"(g));
}
__device__ __forceinline__ void cp_commit() {
    asm volatile("cp.async.commit_group;\n" ::);
}
__device__ __forceinline__ void cp_wait0() {
    asm volatile("cp.async.wait_group 0;\n" ::);
}
__device__ __forceinline__ void cp_wait1() {
    asm volatile("cp.async.wait_group 1;\n" ::);
}
__device__ __forceinline__ void cp_wait2() {
    asm volatile("cp.async.wait_group 2;\n" ::);
}
__device__ __forceinline__ uint32_t smem_u32(const void* p) {
    uint32_t a;
    asm("{ .reg .u64 t; cvta.to.shared.u64 t, %1; cvt.u32.u64 %0, t; }"
        : "=r"(a) : "l"(p));
    return a;
}

// ---------------------------------------------------------------------------
// Pre-pass: round Q,K,V inputs and the 4 weight matrices to canonical tf32.
// ---------------------------------------------------------------------------
__global__ __launch_bounds__(256) void round_pre(
    const float* __restrict__ Q, const float* __restrict__ K, const float* __restrict__ V,
    const float* __restrict__ W0, const float* __restrict__ W1,
    const float* __restrict__ W2, const float* __restrict__ W3,
    float* __restrict__ rq, float* __restrict__ rk, float* __restrict__ rv,
    float* __restrict__ rw)
{
    const int z = blockIdx.y;
    const float4* src;
    float4* dst;
    int n;
    if (z == 0)      { src = (const float4*)Q;  dst = (float4*)rq; n = MROWS * EMB / 4; }
    else if (z == 1) { src = (const float4*)K;  dst = (float4*)rk; n = MROWS * EMB / 4; }
    else if (z == 2) { src = (const float4*)V;  dst = (float4*)rv; n = MROWS * EMB / 4; }
    else {
        const float* w = (z == 3) ? W0 : (z == 4) ? W1 : (z == 5) ? W2 : W3;
        src = (const float4*)w;
        dst = (float4*)(rw + (size_t)(z - 3) * EMB * EMB);
        n = EMB * EMB / 4;
    }
    int i = blockIdx.x * 256 + threadIdx.x;
    if (i < n) dst[i] = tf32x4(src[i]);
}

// ---------------------------------------------------------------------------
// TF32 tensor-core GEMM, cp.async 3-stage pipeline, z-batched over up to 3
// independent problems. Inputs MUST be pre-rounded tf32. (R12-validated.)
// 256 threads (8 warps), warp tile 64x32, BM=128, BN=128, BK=32, m16n8k8.
// ---------------------------------------------------------------------------
#define GSTAGES 3
#define ASE (128 * 36)
#define BSE (32 * 136)
#define GEMM_SMEM_BYTES (GSTAGES * (ASE + BSE) * 4)   // 107520

__global__ __launch_bounds__(256, 2) void gemm_tc3(
    const float* __restrict__ A0, const float* __restrict__ A1, const float* __restrict__ A2,
    const float* __restrict__ W0, const float* __restrict__ W1, const float* __restrict__ W2,
    const float* __restrict__ b0, const float* __restrict__ b1, const float* __restrict__ b2,
    float* __restrict__ C0, float* __restrict__ C1, float* __restrict__ C2,
    int M, int N, int K, int roundC)
{
    extern __shared__ float smg[];

    const int z = blockIdx.z;
    const float* A    = (z == 0) ? A0 : (z == 1) ? A1 : A2;
    const float* W    = (z == 0) ? W0 : (z == 1) ? W1 : W2;
    const float* bias = (z == 0) ? b0 : (z == 1) ? b1 : b2;
    float*       C    = (z == 0) ? C0 : (z == 1) ? C1 : C2;

    const int tid  = threadIdx.x;
    const int lane = tid & 31;
    const int wid  = tid >> 5;      // 0..7
    const int wm   = wid & 1;       // 2 warps along M (64 each)
    const int wn   = wid >> 1;      // 4 warps along N (32 each)
    const int bm   = blockIdx.y;
    const int bn   = blockIdx.x;
    const int grp  = lane >> 2;
    const int tig  = lane & 3;

    const float* Abase = A + (size_t)(bm * 128) * K;
    const float* Wbase = W + bn * 128;
    const uint32_t sbase = (uint32_t)__cvta_generic_to_shared(smg);

    float acc[4][4][4];
    #pragma unroll
    for (int i = 0; i < 4; i++)
        #pragma unroll
        for (int j = 0; j < 4; j++)
            #pragma unroll
            for (int q = 0; q < 4; q++) acc[i][j][q] = 0.f;

    auto issue_stage = [&](int s, int k0) {
        #pragma unroll
        for (int i = 0; i < 4; i++) {
            int idx = tid + 256 * i;
            int r = idx >> 3, c = (idx & 7) << 2;
            uint32_t dst = sbase + (uint32_t)((s * ASE + r * 36 + c) * 4);
            cp_async16(dst, Abase + (size_t)r * K + k0 + c);
        }
        #pragma unroll
        for (int i = 0; i < 4; i++) {
            int idx = tid + 256 * i;
            int r = idx >> 5, c = (idx & 31) << 2;
            uint32_t dst = sbase + (uint32_t)((GSTAGES * ASE + s * BSE + r * 136 + c) * 4);
            cp_async16(dst, Wbase + (size_t)(k0 + r) * N + c);
        }
    };

    issue_stage(0, 0);  cp_commit();
    issue_stage(1, 32); cp_commit();

    int s = 0;
    for (int k0 = 0; k0 < K; k0 += 32) {
        cp_wait1();          // stage s complete (2 groups max in flight)
        __syncthreads();     // make it visible to all warps

        if (k0 + 64 < K) issue_stage((s + 2) % 3, k0 + 64);
        cp_commit();         // commit (possibly empty) to keep group counts uniform

        const float* aS = smg + s * ASE;
        const float* bS = smg + GSTAGES * ASE + s * BSE;

        #pragma unroll
        for (int ks = 0; ks < 4; ks++) {
            const int kb = ks * 8;
            uint32_t af[4][4];
            #pragma unroll
            for (int mf = 0; mf < 4; mf++) {
                const float* p0 = aS + (wm * 64 + mf * 16 + grp) * 36 + kb + tig;
                const float* p1 = p0 + 8 * 36;
                af[mf][0] = __float_as_uint(p0[0]);
                af[mf][1] = __float_as_uint(p1[0]);
                af[mf][2] = __float_as_uint(p0[4]);
                af[mf][3] = __float_as_uint(p1[4]);
            }
            uint32_t bf[4][2];
            #pragma unroll
            for (int nf = 0; nf < 4; nf++) {
                const float* q0 = bS + (kb + tig) * 136 + wn * 32 + nf * 8 + grp;
                bf[nf][0] = __float_as_uint(q0[0]);
                bf[nf][1] = __float_as_uint(q0[4 * 136]);
            }
            #pragma unroll
            for (int mf = 0; mf < 4; mf++)
                #pragma unroll
                for (int nf = 0; nf < 4; nf++)
                    mma_tf32(acc[mf][nf], af[mf], bf[nf]);
        }
        s = (s + 1) % 3;
    }

    float2 bb[4];
    #pragma unroll
    for (int nf = 0; nf < 4; nf++)
        bb[nf] = *(const float2*)(bias + bn * 128 + wn * 32 + nf * 8 + tig * 2);

    #pragma unroll
    for (int mf = 0; mf < 4; mf++) {
        int row0 = bm * 128 + wm * 64 + mf * 16 + grp;
        #pragma unroll
        for (int nf = 0; nf < 4; nf++) {
            int col = bn * 128 + wn * 32 + nf * 8 + tig * 2;
            float2 v0, v1;
            v0.x = acc[mf][nf][0] + bb[nf].x;
            v0.y = acc[mf][nf][1] + bb[nf].y;
            v1.x = acc[mf][nf][2] + bb[nf].x;
            v1.y = acc[mf][nf][3] + bb[nf].y;
            if (roundC) {
                v0.x = to_tf32(v0.x); v0.y = to_tf32(v0.y);
                v1.x = to_tf32(v1.x); v1.y = to_tf32(v1.y);
            }
            *(float2*)(C + (size_t)row0 * N + col)       = v0;
            *(float2*)(C + (size_t)(row0 + 8) * N + col) = v1;
        }
    }
}

// ---------------------------------------------------------------------------
// Tensor-core causal flash attention (TF32 mma.sync, FA2-style).
// BM=64, 128 threads (4 warps x 16 query rows), 3 CTAs/SM.
// R14: software-pipelined KV — 2 K slots (ring) + 1 V slot.
//   tile j: wait0 (K_j landed an iter ago) -> sync -> issue V_j & K_{j+1}
//           -> QK+softmax -> wait1 (V_j landed during QK) -> sync -> PV.
// Both cp waits are ~free; only tile 0 pays one cold K latency.
// Smem: Ps[64][68] + Ks0[64][68] + Ks1[64][68] + Vs[64][72] = 70656 B.
// ---------------------------------------------------------------------------
#define BM 64
#define PS_STRIDE 68
#define KS_STRIDE 68
#define VS_STRIDE 72
#define OFF_K0 (BM * PS_STRIDE)
#define OFF_K1 (OFF_K0 + 64 * KS_STRIDE)
#define OFF_VS (OFF_K1 + 64 * KS_STRIDE)
#define SMEM_FLASH_BYTES ((OFF_VS + 64 * VS_STRIDE) * 4)   // 70656

__global__ __launch_bounds__(128, 3) void flash_tc(
    const float* __restrict__ Qp, const float* __restrict__ Kp,
    const float* __restrict__ Vp, float* __restrict__ Op)
{
    extern __shared__ float sm[];
    float* Ps  = sm;
    float* Ks0 = sm + OFF_K0;
    float* Ks1 = sm + OFF_K1;
    float* Vs  = sm + OFF_VS;

    const int bh = blockIdx.y;
    const int b  = bh >> 4, h = bh & 15;
    const int m0 = blockIdx.x * BM;
    const int t  = threadIdx.x, lane = t & 31, w = t >> 5;   // w: 0..3
    const int grp = lane >> 2, tig = lane & 3;

    const float* Qbase = Qp + (size_t)b * SEQ * EMB + h * HDIM;
    const float* Kbase = Kp + (size_t)b * SEQ * EMB + h * HDIM;
    const float* Vbase = Vp + (size_t)b * SEQ * EMB + h * HDIM;
    const uint32_t sK0 = smem_u32(Ks0);
    const uint32_t sK1 = smem_u32(Ks1);
    const uint32_t sVs = smem_u32(Vs);

    // Stage Q tile (rows m0..m0+63) into Ps (already tf32-rounded).
    #pragma unroll
    for (int i = 0; i < 8; i++) {
        int idx = t + i * 128;
        int r = idx >> 4, c4 = idx & 15;
        *(float4*)(Ps + r * PS_STRIDE + c4 * 4) =
            *(const float4*)(Qbase + (size_t)(m0 + r) * EMB + c4 * 4);
    }

    auto issue_K = [&](int n0, uint32_t sKslot) {
        #pragma unroll
        for (int i = 0; i < 8; i++) {
            int idx = t + i * 128;
            int r = idx >> 4, c4 = idx & 15;
            cp_async16(sKslot + (uint32_t)((r * KS_STRIDE + c4 * 4) * 4),
                       Kbase + (size_t)(n0 + r) * EMB + c4 * 4);
        }
    };
    auto issue_V = [&](int n0) {
        #pragma unroll
        for (int i = 0; i < 8; i++) {
            int idx = t + i * 128;
            int r = idx >> 4, c4 = idx & 15;
            cp_async16(sVs + (uint32_t)((r * VS_STRIDE + c4 * 4) * 4),
                       Vbase + (size_t)(n0 + r) * EMB + c4 * 4);
        }
    };

    // Prologue: K tile 0 in flight; barrier also publishes Ps(Q).
    issue_K(0, sK0);
    cp_commit();
    __syncthreads();

    // Persistent Q a-fragments (m16k8 x 8 k-steps).
    const int qr = w * 16 + grp;
    uint32_t qf[8][4];
    #pragma unroll
    for (int kf = 0; kf < 8; kf++) {
        const float* p0 = Ps + qr * PS_STRIDE + kf * 8 + tig;
        const float* p1 = p0 + 8 * PS_STRIDE;
        qf[kf][0] = __float_as_uint(p0[0]);
        qf[kf][1] = __float_as_uint(p1[0]);
        qf[kf][2] = __float_as_uint(p0[4]);
        qf[kf][3] = __float_as_uint(p1[4]);
    }

    float of[8][4];
    #pragma unroll
    for (int nf = 0; nf < 8; nf++)
        #pragma unroll
        for (int q = 0; q < 4; q++) of[nf][q] = 0.f;
    float mm0 = -INFINITY, mm1 = -INFINITY, ll0 = 0.f, ll1 = 0.f;

    const int rowMin = m0 + w * 16;
    const int rowMax = rowMin + 15;
    const int i0 = rowMin + grp;
    const int i1 = i0 + 8;

    const int nT = m0 / 64 + 1;   // KV tiles (causal bound)
    for (int j = 0; j < nT; j++) {
        const int n0 = j * 64;
        const float* Kcur = (j & 1) ? Ks1 : Ks0;

        cp_wait0();        // K_j (and older) complete
        __syncthreads();   // K_j visible; V slot + other K slot free

        issue_V(n0);
        cp_commit();
        if (j + 1 < nT) issue_K((j + 1) * 64, (j & 1) ? sK0 : sK1);
        cp_commit();       // empty group when last tile: counts stay uniform

        const bool skip = (n0 > rowMax);   // warp-uniform

        float sf[8][4];
        if (!skip) {
            // --- S = Q @ K^T ---
            #pragma unroll
            for (int nf = 0; nf < 8; nf++)
                #pragma unroll
                for (int q = 0; q < 4; q++) sf[nf][q] = 0.f;

            #pragma unroll
            for (int nf = 0; nf < 8; nf++) {
                const float* kb = Kcur + (nf * 8 + grp) * KS_STRIDE + tig;
                #pragma unroll
                for (int kf = 0; kf < 8; kf++) {
                    uint32_t bfr[2];
                    bfr[0] = __float_as_uint(kb[kf * 8]);
                    bfr[1] = __float_as_uint(kb[kf * 8 + 4]);
                    mma_tf32(sf[nf], qf[kf], bfr);
                }
            }

            // --- scale (log2 space) + causal mask ---
            const bool fullT = (n0 + 63 <= rowMin);
            #pragma unroll
            for (int nf = 0; nf < 8; nf++) {
                #pragma unroll
                for (int q = 0; q < 4; q++) sf[nf][q] *= SLOG2;
                if (!fullT) {
                    int j0 = n0 + nf * 8 + 2 * tig;
                    if (j0     > i0) sf[nf][0] = -INFINITY;
                    if (j0 + 1 > i0) sf[nf][1] = -INFINITY;
                    if (j0     > i1) sf[nf][2] = -INFINITY;
                    if (j0 + 1 > i1) sf[nf][3] = -INFINITY;
                }
            }

            // --- online softmax (rows live in 4 consecutive lanes) ---
            float mx0 = -INFINITY, mx1 = -INFINITY;
            #pragma unroll
            for (int nf = 0; nf < 8; nf++) {
                mx0 = fmaxf(mx0, fmaxf(sf[nf][0], sf[nf][1]));
                mx1 = fmaxf(mx1, fmaxf(sf[nf][2], sf[nf][3]));
            }
            mx0 = fmaxf(mx0, __shfl_xor_sync(0xffffffffu, mx0, 1));
            mx0 = fmaxf(mx0, __shfl_xor_sync(0xffffffffu, mx0, 2));
            mx1 = fmaxf(mx1, __shfl_xor_sync(0xffffffffu, mx1, 1));
            mx1 = fmaxf(mx1, __shfl_xor_sync(0xffffffffu, mx1, 2));

            float nm0 = fmaxf(mm0, mx0), nm1 = fmaxf(mm1, mx1);
            float c0 = fast_exp2(mm0 - nm0), c1 = fast_exp2(mm1 - nm1);
            mm0 = nm0; mm1 = nm1;

            float s0 = 0.f, s1 = 0.f;
            float* pr0 = Ps + qr * PS_STRIDE + 2 * tig;
            float* pr1 = pr0 + 8 * PS_STRIDE;
            #pragma unroll
            for (int nf = 0; nf < 8; nf++) {
                float p00 = to_tf32(fast_exp2(sf[nf][0] - nm0));
                float p01 = to_tf32(fast_exp2(sf[nf][1] - nm0));
                float p10 = to_tf32(fast_exp2(sf[nf][2] - nm1));
                float p11 = to_tf32(fast_exp2(sf[nf][3] - nm1));
                s0 += p00 + p01;
                s1 += p10 + p11;
                *(float2*)(pr0 + nf * 8) = make_float2(p00, p01);
                *(float2*)(pr1 + nf * 8) = make_float2(p10, p11);
                of[nf][0] *= c0; of[nf][1] *= c0;
                of[nf][2] *= c1; of[nf][3] *= c1;
            }
            s0 += __shfl_xor_sync(0xffffffffu, s0, 1);
            s0 += __shfl_xor_sync(0xffffffffu, s0, 2);
            s1 += __shfl_xor_sync(0xffffffffu, s1, 1);
            s1 += __shfl_xor_sync(0xffffffffu, s1, 2);
            ll0 = ll0 * c0 + s0;
            ll1 = ll1 * c1 + s1;
            __syncwarp();   // P rows are warp-private
        }

        cp_wait1();        // V_j complete (K_{j+1} may be in flight)
        __syncthreads();   // V_j visible to all warps

        if (!skip) {
            // --- O += P @ V ---
            uint32_t af[8][4];
            #pragma unroll
            for (int kf = 0; kf < 8; kf++) {
                const float* a0 = Ps + qr * PS_STRIDE + kf * 8 + tig;
                const float* a1 = a0 + 8 * PS_STRIDE;
                af[kf][0] = __float_as_uint(a0[0]);
                af[kf][1] = __float_as_uint(a1[0]);
                af[kf][2] = __float_as_uint(a0[4]);
                af[kf][3] = __float_as_uint(a1[4]);
            }
            #pragma unroll
            for (int nf = 0; nf < 8; nf++) {
                #pragma unroll
                for (int kf = 0; kf < 8; kf++) {
                    uint32_t bfr[2];
                    const float* vb = Vs + (kf * 8 + tig) * VS_STRIDE + nf * 8 + grp;
                    bfr[0] = __float_as_uint(vb[0]);
                    bfr[1] = __float_as_uint(vb[4 * VS_STRIDE]);
                    mma_tf32(of[nf], af[kf], bfr);
                }
            }
        }
    }

    // --- epilogue: normalize, round to tf32 (feeds out-projection), store ---
    const float inv0 = 1.f / ll0;
    const float inv1 = 1.f / ll1;
    float* O0 = Op + (size_t)(b * SEQ + m0 + w * 16 + grp) * EMB + h * HDIM + 2 * tig;
    float* O1 = O0 + (size_t)8 * EMB;
    #pragma unroll
    for (int nf = 0; nf < 8; nf++) {
        *(float2*)(O0 + nf * 8) = make_float2(to_tf32(of[nf][0] * inv0),
                                              to_tf32(of[nf][1] * inv0));
        *(float2*)(O1 + nf * 8) = make_float2(to_tf32(of[nf][2] * inv1),
                                              to_tf32(of[nf][3] * inv1));
    }
}

// ---------------------------------------------------------------------------
// Launch
// ---------------------------------------------------------------------------
extern "C" void kernel_launch(void* const* d_in, const int* in_sizes, int n_in,
                              void* d_out, int out_size)
{
    const float* Q  = (const float*)d_in[0];
    const float* K  = (const float*)d_in[1];
    const float* V  = (const float*)d_in[2];
    const float* WQ = (const float*)d_in[3];
    const float* bQ = (const float*)d_in[4];
    const float* WK = (const float*)d_in[5];
    const float* bK = (const float*)d_in[6];
    const float* WV = (const float*)d_in[7];
    const float* bV = (const float*)d_in[8];
    const float* WO = (const float*)d_in[9];
    const float* bO = (const float*)d_in[10];
    float* out = (float*)d_out;

    float *gq, *gk, *gv, *ga, *grq, *grk, *grv, *gw;
    cudaGetSymbolAddress((void**)&gq,  g_q);
    cudaGetSymbolAddress((void**)&gk,  g_k);
    cudaGetSymbolAddress((void**)&gv,  g_v);
    cudaGetSymbolAddress((void**)&ga,  g_att);
    cudaGetSymbolAddress((void**)&grq, g_rq);
    cudaGetSymbolAddress((void**)&grk, g_rk);
    cudaGetSymbolAddress((void**)&grv, g_rv);
    cudaGetSymbolAddress((void**)&gw,  g_w);

    cudaFuncSetAttribute(gemm_tc3, cudaFuncAttributeMaxDynamicSharedMemorySize,
                         GEMM_SMEM_BYTES);
    cudaFuncSetAttribute(flash_tc, cudaFuncAttributeMaxDynamicSharedMemorySize,
                         SMEM_FLASH_BYTES);

    // Pre-round inputs + weights to canonical tf32
    round_pre<<<dim3(8192, 7), 256>>>(Q, K, V, WQ, WK, WV, WO,
                                      grq, grk, grv, gw);

    // Fused Q/K/V projections (outputs rounded to tf32 for flash)
    dim3 gqkv(EMB / 128, MROWS / 128, 3);  // (8, 64, 3)
    gemm_tc3<<<gqkv, 256, GEMM_SMEM_BYTES>>>(
        grq, grk, grv,
        gw, gw + (size_t)EMB * EMB, gw + (size_t)2 * EMB * EMB,
        bQ, bK, bV, gq, gk, gv, MROWS, EMB, EMB, 1);

    dim3 fg(SEQ / BM, BATCH * HEADS);      // (32, 64)
    flash_tc<<<fg, 128, SMEM_FLASH_BYTES>>>(gq, gk, gv, ga);

    // Output projection (256 threads!)
    dim3 go(EMB / 128, MROWS / 128, 1);
    const float* gwo = gw + (size_t)3 * EMB * EMB;
    gemm_tc3<<<go, 256, GEMM_SMEM_BYTES>>>(
        ga, ga, ga, gwo, gwo, gwo, bO, bO, bO,
        out, out, out, MROWS, EMB, EMB, 0);
}